// round 1
// baseline (speedup 1.0000x reference)
#include <cuda_runtime.h>
#include <cuda_bf16.h>
#include <cstdint>

// Problem constants
#define NN      29040        // nodes (121*240)
#define EE      464640       // edges (NN*16)
#define HH      128          // hidden
#define LVV     11           // levels
#define EIN     290          // 2*H + 33 + 1
#define NLAT    121
#define NLON    240

// Edge kernel tiling
#define ETILE   64
#define SA_STR  292          // padded 290 (multiple of 4 for float4)
#define SB_STR  132          // padded 128

// Node kernel tiling
#define NTILE   64
#define NA_STR  384          // 3*H, already multiple of 4

// ---- scratch (no allocation allowed) ----
__device__ float g_agg[NN * HH];      // scatter-sum of edge_feat
__device__ float g_wind[NN * 22];     // scatter-sum of wind (u:0..10, v:11..21)
__device__ float g_cnt[NN];           // edges per row
__device__ float g_lat[NLAT * HH];    // lat-band means

// ============================================================
__global__ void zero_kernel() {
    int i = blockIdx.x * 256 + threadIdx.x;
    if (i < NN * HH) g_agg[i] = 0.f;
    if (i < NN * 22) g_wind[i] = 0.f;
    if (i < NN)      g_cnt[i] = 0.f;
}

// ============================================================
// Fused edge pass: gather -> edgeMLP -> scatter agg -> coordMLP -> scatter wind
__global__ __launch_bounds__(256, 2)
void edge_kernel(const float* __restrict__ h,
                 const float* __restrict__ u,
                 const float* __restrict__ v,
                 const float* __restrict__ edge_attr,
                 const float* __restrict__ W_e1, const float* __restrict__ b_e1,
                 const float* __restrict__ W_e2, const float* __restrict__ b_e2,
                 const float* __restrict__ W_c1, const float* __restrict__ b_c1,
                 const float* __restrict__ W_cl,
                 const int*   __restrict__ edge_index)
{
    extern __shared__ __align__(16) float smem[];
    float* sA   = smem;                       // [ETILE][SA_STR]
    float* sB   = sA + ETILE * SA_STR;        // [ETILE][SB_STR]
    int*   sRow = (int*)(sB + ETILE * SB_STR);// [ETILE]
    float* sRad = (float*)(sRow + ETILE);     // [ETILE][2]

    const int tid = threadIdx.x;
    const int e0  = blockIdx.x * ETILE;

    // ---- gather h[row], h[col] (4 threads per edge, float4) ----
    {
        int e = tid >> 2, sub = tid & 3;
        int g = e0 + e;
        int r = edge_index[g];
        int c = edge_index[EE + g];
        const float4* hr = (const float4*)(h + (size_t)r * HH);
        const float4* hc = (const float4*)(h + (size_t)c * HH);
        float4* dst = (float4*)(sA + e * SA_STR);
        #pragma unroll
        for (int i = 0; i < 8; i++) dst[sub + 4*i]      = hr[sub + 4*i];
        #pragma unroll
        for (int i = 0; i < 8; i++) dst[32 + sub + 4*i] = hc[sub + 4*i];
        if (sub == 0) {
            sRow[e] = r;
            sA[e * SA_STR + 289] = edge_attr[g];
            sA[e * SA_STR + 290] = 0.f;
            sA[e * SA_STR + 291] = 0.f;
            atomicAdd(&g_cnt[r], 1.0f);
        }
    }

    // ---- w_diff: rel_dirt / col_speed / row_speed ----
    for (int idx = tid; idx < ETILE * LVV; idx += 256) {
        int e = idx / LVV, lv = idx - e * LVV;
        int g = e0 + e;
        int r = edge_index[g], c = edge_index[EE + g];
        float ucv = u[c * LVV + lv], vcv = v[c * LVV + lv];
        float urv = u[r * LVV + lv], vrv = v[r * LVV + lv];
        float cs = sqrtf(ucv * ucv + vcv * vcv);
        float rs = sqrtf(urv * urv + vrv * vrv);
        float rd = (ucv * urv + vcv * vrv) / (cs * rs);
        float* rrow = sA + e * SA_STR;
        rrow[256 + lv] = rd;
        rrow[267 + lv] = cs;
        rrow[278 + lv] = rs;
    }

    // ---- rad2 per edge (|| u[col] ||, || v[col] ||) ----
    for (int e = tid; e < ETILE; e += 256) {
        int g = e0 + e;
        int c = edge_index[EE + g];
        float su = 0.f, sv = 0.f;
        #pragma unroll
        for (int lv = 0; lv < LVV; lv++) {
            float a = u[c * LVV + lv], b = v[c * LVV + lv];
            su += a * a; sv += b * b;
        }
        sRad[e * 2 + 0] = sqrtf(su);
        sRad[e * 2 + 1] = sqrtf(sv);
    }
    __syncthreads();

    const int j  = tid & 127;
    const int eg = tid >> 7;      // 0 or 1: edge half

    // ---- GEMM1: hid = relu(edge_in @ W_e1 + b_e1) : sA(290) -> sB(128) ----
    {
        float acc[32];
        #pragma unroll
        for (int e = 0; e < 32; e++) acc[e] = 0.f;
        const float* base = sA + (eg * 32) * SA_STR;
        for (int k = 0; k < 288; k += 4) {
            float w0 = W_e1[(k+0)*HH + j], w1 = W_e1[(k+1)*HH + j];
            float w2 = W_e1[(k+2)*HH + j], w3 = W_e1[(k+3)*HH + j];
            #pragma unroll
            for (int e = 0; e < 32; e++) {
                float4 a = *(const float4*)(base + e * SA_STR + k);
                acc[e] += a.x*w0 + a.y*w1 + a.z*w2 + a.w*w3;
            }
        }
        {   // tail k = 288,289
            float w0 = W_e1[288*HH + j], w1 = W_e1[289*HH + j];
            #pragma unroll
            for (int e = 0; e < 32; e++) {
                const float* rr = base + e * SA_STR;
                acc[e] += rr[288]*w0 + rr[289]*w1;
            }
        }
        float bb = b_e1[j];
        #pragma unroll
        for (int e = 0; e < 32; e++)
            sB[(eg*32 + e)*SB_STR + j] = fmaxf(acc[e] + bb, 0.f);
    }
    __syncthreads();

    // ---- GEMM2: feat = relu(hid @ W_e2 + b_e2) : sB -> sA[0..127] ----
    {
        float acc[32];
        #pragma unroll
        for (int e = 0; e < 32; e++) acc[e] = 0.f;
        const float* base = sB + (eg * 32) * SB_STR;
        for (int k = 0; k < 128; k += 4) {
            float w0 = W_e2[(k+0)*HH + j], w1 = W_e2[(k+1)*HH + j];
            float w2 = W_e2[(k+2)*HH + j], w3 = W_e2[(k+3)*HH + j];
            #pragma unroll
            for (int e = 0; e < 32; e++) {
                float4 a = *(const float4*)(base + e * SB_STR + k);
                acc[e] += a.x*w0 + a.y*w1 + a.z*w2 + a.w*w3;
            }
        }
        float bb = b_e2[j];
        #pragma unroll
        for (int e = 0; e < 32; e++)
            sA[(eg*32 + e)*SA_STR + j] = fmaxf(acc[e] + bb, 0.f);
    }
    __syncthreads();

    // ---- scatter agg += feat (vector atomics) ----
    for (int idx = tid; idx < ETILE * 32; idx += 256) {
        int e = idx >> 5, q = idx & 31;
        float4 val = *(const float4*)(sA + e * SA_STR + q * 4);
        float* dst = g_agg + (size_t)sRow[e] * HH + q * 4;
        asm volatile("red.global.add.v4.f32 [%0], {%1,%2,%3,%4};"
                     :: "l"(dst), "f"(val.x), "f"(val.y), "f"(val.z), "f"(val.w)
                     : "memory");
    }

    // ---- coord GEMM1: c1 = relu(feat @ W_c1 + b_c1) : sA -> sB ----
    {
        float acc[32];
        #pragma unroll
        for (int e = 0; e < 32; e++) acc[e] = 0.f;
        const float* base = sA + (eg * 32) * SA_STR;
        for (int k = 0; k < 128; k += 4) {
            float w0 = W_c1[(k+0)*HH + j], w1 = W_c1[(k+1)*HH + j];
            float w2 = W_c1[(k+2)*HH + j], w3 = W_c1[(k+3)*HH + j];
            #pragma unroll
            for (int e = 0; e < 32; e++) {
                float4 a = *(const float4*)(base + e * SA_STR + k);
                acc[e] += a.x*w0 + a.y*w1 + a.z*w2 + a.w*w3;
            }
        }
        float bb = b_c1[j];
        #pragma unroll
        for (int e = 0; e < 32; e++)
            sB[(eg*32 + e)*SB_STR + j] = fmaxf(acc[e] + bb, 0.f);
    }
    __syncthreads();

    // ---- coord GEMM2 (H->22) * rad2, scatter wind ----
    for (int idx = tid; idx < ETILE * 22; idx += 256) {
        int e = idx / 22, m = idx - e * 22;
        const float* brow = sB + e * SB_STR;
        float acc = 0.f;
        #pragma unroll 8
        for (int k = 0; k < 128; k++)
            acc += brow[k] * W_cl[k * 22 + m];
        float r2 = sRad[e * 2 + (m >= 11 ? 1 : 0)];
        atomicAdd(&g_wind[(size_t)sRow[e] * 22 + m], acc * r2);
    }
}

// ============================================================
__global__ void lat_kernel() {
    int lt = blockIdx.x;          // 0..120
    int jj = threadIdx.x;         // 0..127
    float s = 0.f;
    for (int lon = 0; lon < NLON; lon++)
        s += g_agg[((size_t)lt * NLON + lon) * HH + jj];
    g_lat[lt * HH + jj] = s * (1.0f / NLON);
}

// ============================================================
// Node MLP: h_out = relu([h,agg,lat] @ W_n1 + b_n1) @ W_n2 + b_n2 + h
__global__ __launch_bounds__(256, 1)
void node_kernel(const float* __restrict__ h,
                 const float* __restrict__ W_n1, const float* __restrict__ b_n1,
                 const float* __restrict__ W_n2, const float* __restrict__ b_n2,
                 float* __restrict__ out)
{
    extern __shared__ __align__(16) float smem[];
    float* sA = smem;                  // [NTILE][NA_STR]
    float* sB = sA + NTILE * NA_STR;   // [NTILE][SB_STR]

    const int tid = threadIdx.x;
    const int n0  = blockIdx.x * NTILE;

    {
        int e = tid >> 2, sub = tid & 3;
        int n = n0 + e;
        float4* dst = (float4*)(sA + e * NA_STR);
        if (n < NN) {
            const float4* hh = (const float4*)(h + (size_t)n * HH);
            const float4* aa = (const float4*)(g_agg + (size_t)n * HH);
            const float4* ll = (const float4*)(g_lat + (size_t)(n / NLON) * HH);
            #pragma unroll
            for (int i = 0; i < 8; i++) {
                dst[sub + 4*i]      = hh[sub + 4*i];
                dst[32 + sub + 4*i] = aa[sub + 4*i];
                dst[64 + sub + 4*i] = ll[sub + 4*i];
            }
        } else {
            float4 z = make_float4(0.f, 0.f, 0.f, 0.f);
            #pragma unroll
            for (int i = 0; i < 8; i++) {
                dst[sub + 4*i] = z; dst[32 + sub + 4*i] = z; dst[64 + sub + 4*i] = z;
            }
        }
    }
    __syncthreads();

    const int j  = tid & 127;
    const int eg = tid >> 7;

    // GEMM1: [64,384]@[384,128], relu -> sB
    {
        float acc[32];
        #pragma unroll
        for (int e = 0; e < 32; e++) acc[e] = 0.f;
        const float* base = sA + (eg * 32) * NA_STR;
        for (int k = 0; k < NA_STR; k += 4) {
            float w0 = W_n1[(k+0)*HH + j], w1 = W_n1[(k+1)*HH + j];
            float w2 = W_n1[(k+2)*HH + j], w3 = W_n1[(k+3)*HH + j];
            #pragma unroll
            for (int e = 0; e < 32; e++) {
                float4 a = *(const float4*)(base + e * NA_STR + k);
                acc[e] += a.x*w0 + a.y*w1 + a.z*w2 + a.w*w3;
            }
        }
        float bb = b_n1[j];
        #pragma unroll
        for (int e = 0; e < 32; e++)
            sB[(eg*32 + e)*SB_STR + j] = fmaxf(acc[e] + bb, 0.f);
    }
    __syncthreads();

    // GEMM2: [64,128]@[128,128] + b + residual -> out
    {
        float acc[32];
        #pragma unroll
        for (int e = 0; e < 32; e++) acc[e] = 0.f;
        const float* base = sB + (eg * 32) * SB_STR;
        for (int k = 0; k < 128; k += 4) {
            float w0 = W_n2[(k+0)*HH + j], w1 = W_n2[(k+1)*HH + j];
            float w2 = W_n2[(k+2)*HH + j], w3 = W_n2[(k+3)*HH + j];
            #pragma unroll
            for (int e = 0; e < 32; e++) {
                float4 a = *(const float4*)(base + e * SB_STR + k);
                acc[e] += a.x*w0 + a.y*w1 + a.z*w2 + a.w*w3;
            }
        }
        float bb = b_n2[j];
        #pragma unroll
        for (int e = 0; e < 32; e++) {
            int n = n0 + eg*32 + e;
            if (n < NN)
                out[(size_t)n * HH + j] = acc[e] + bb + h[(size_t)n * HH + j];
        }
    }
}

// ============================================================
__global__ void coord_kernel(float* __restrict__ out) {
    int i = blockIdx.x * 256 + threadIdx.x;     // over NN*22
    if (i >= NN * 22) return;
    int n = i / 22, m = i - n * 22;
    float cnt = fmaxf(g_cnt[n], 1.0f);
    float val = g_wind[i] / cnt;
    val = fminf(fmaxf(val, -100.0f), 100.0f);
    int lv = (m >= 11) ? (m - 11) : m;
    float* o = out + (size_t)NN * HH + (m >= 11 ? NN * LVV : 0) + n * LVV + lv;
    *o = val;
}

// ============================================================
extern "C" void kernel_launch(void* const* d_in, const int* in_sizes, int n_in,
                              void* d_out, int out_size)
{
    const float* h         = (const float*)d_in[0];
    const float* u         = (const float*)d_in[1];
    const float* v         = (const float*)d_in[2];
    const float* edge_attr = (const float*)d_in[3];
    const float* W_e1      = (const float*)d_in[4];
    const float* b_e1      = (const float*)d_in[5];
    const float* W_e2      = (const float*)d_in[6];
    const float* b_e2      = (const float*)d_in[7];
    const float* W_n1      = (const float*)d_in[8];
    const float* b_n1      = (const float*)d_in[9];
    const float* W_n2      = (const float*)d_in[10];
    const float* b_n2      = (const float*)d_in[11];
    const float* W_c1      = (const float*)d_in[12];
    const float* b_c1      = (const float*)d_in[13];
    const float* W_cl      = (const float*)d_in[14];
    const int*   edge_index= (const int*)  d_in[15];
    float* out = (float*)d_out;

    const int EDGE_SMEM = (ETILE * SA_STR + ETILE * SB_STR) * 4 + ETILE * 4 + ETILE * 2 * 4;
    const int NODE_SMEM = (NTILE * NA_STR + NTILE * SB_STR) * 4;
    cudaFuncSetAttribute(edge_kernel, cudaFuncAttributeMaxDynamicSharedMemorySize, EDGE_SMEM);
    cudaFuncSetAttribute(node_kernel, cudaFuncAttributeMaxDynamicSharedMemorySize, NODE_SMEM);

    zero_kernel<<<(NN * HH + 255) / 256, 256>>>();

    edge_kernel<<<EE / ETILE, 256, EDGE_SMEM>>>(h, u, v, edge_attr,
                                                W_e1, b_e1, W_e2, b_e2,
                                                W_c1, b_c1, W_cl, edge_index);

    lat_kernel<<<NLAT, HH>>>();

    node_kernel<<<(NN + NTILE - 1) / NTILE, 256, NODE_SMEM>>>(h, W_n1, b_n1, W_n2, b_n2, out);

    coord_kernel<<<(NN * 22 + 255) / 256, 256>>>(out);
}

// round 3
// speedup vs baseline: 1.5636x; 1.5636x over previous
#include <cuda_runtime.h>
#include <cuda_bf16.h>
#include <cstdint>

// Problem constants
#define NN      29040        // nodes (121*240)
#define EE      464640       // edges (NN*16)
#define HH      128          // hidden
#define LVV     11           // levels
#define NLAT    121
#define NLON    240

// Edge kernel tiling
#define ETILE   64
#define SI_STR  36           // w_diff(33)+attr(1), padded
#define SB_STR  132          // padded 128

// Node kernel tiling
#define NTILE   32
#define NA_STR  384          // 3*H

// ---- scratch (no allocation allowed) ----
__device__ float g_agg[NN * HH];      // scatter-sum of edge_feat
__device__ float g_wind[NN * 22];     // scatter-sum of wind
__device__ float g_cnt[NN];           // edges per row
__device__ float g_lat[NLAT * HH];    // lat-band means
__device__ float g_PQ[NN * 256];      // P = h@W_e1[0:128] at [n][0:128], Q = h@W_e1[128:256] at [n][128:256]

// ============================================================
__global__ void zero_kernel() {
    int i = blockIdx.x * 256 + threadIdx.x;
    if (i < NN * HH) g_agg[i] = 0.f;
    if (i < NN * 22) g_wind[i] = 0.f;
    if (i < NN)      g_cnt[i] = 0.f;
}

// ============================================================
// Precompute P = h @ W_e1[0:128,:], Q = h @ W_e1[128:256,:]
__global__ __launch_bounds__(256, 2)
void pq_kernel(const float* __restrict__ h,
               const float* __restrict__ W_e1)
{
    extern __shared__ __align__(16) float smem[];
    float* sH = smem;                  // [64][SB_STR]

    const int tid = threadIdx.x;
    const int n0  = blockIdx.x * 64;

    {   // gather 64 rows of h (coalesced)
        int e = tid >> 2, sub = tid & 3;
        int n = n0 + e;
        float4* dst = (float4*)(sH + e * SB_STR);
        if (n < NN) {
            const float4* hh = (const float4*)(h + (size_t)n * HH);
            #pragma unroll
            for (int i = 0; i < 8; i++) dst[sub + 4*i] = hh[sub + 4*i];
        } else {
            float4 z = make_float4(0.f,0.f,0.f,0.f);
            #pragma unroll
            for (int i = 0; i < 8; i++) dst[sub + 4*i] = z;
        }
    }
    __syncthreads();

    const int j  = tid & 127;
    const int eg = tid >> 7;

    // P pass
    {
        float acc[32];
        #pragma unroll
        for (int e = 0; e < 32; e++) acc[e] = 0.f;
        const float* base = sH + (eg * 32) * SB_STR;
        for (int k = 0; k < 128; k += 4) {
            float w0 = W_e1[(k+0)*HH + j], w1 = W_e1[(k+1)*HH + j];
            float w2 = W_e1[(k+2)*HH + j], w3 = W_e1[(k+3)*HH + j];
            #pragma unroll
            for (int e = 0; e < 32; e++) {
                float4 a = *(const float4*)(base + e * SB_STR + k);
                acc[e] += a.x*w0 + a.y*w1 + a.z*w2 + a.w*w3;
            }
        }
        #pragma unroll
        for (int e = 0; e < 32; e++) {
            int n = n0 + eg*32 + e;
            if (n < NN) g_PQ[(size_t)n * 256 + j] = acc[e];
        }
    }
    // Q pass
    {
        const float* Wq = W_e1 + 128 * HH;
        float acc[32];
        #pragma unroll
        for (int e = 0; e < 32; e++) acc[e] = 0.f;
        const float* base = sH + (eg * 32) * SB_STR;
        for (int k = 0; k < 128; k += 4) {
            float w0 = Wq[(k+0)*HH + j], w1 = Wq[(k+1)*HH + j];
            float w2 = Wq[(k+2)*HH + j], w3 = Wq[(k+3)*HH + j];
            #pragma unroll
            for (int e = 0; e < 32; e++) {
                float4 a = *(const float4*)(base + e * SB_STR + k);
                acc[e] += a.x*w0 + a.y*w1 + a.z*w2 + a.w*w3;
            }
        }
        #pragma unroll
        for (int e = 0; e < 32; e++) {
            int n = n0 + eg*32 + e;
            if (n < NN) g_PQ[(size_t)n * 256 + 128 + j] = acc[e];
        }
    }
}

// ============================================================
// Fused edge pass: gather(P+Q) -> small GEMM1 -> GEMM2 -> scatter agg -> coordMLP -> scatter wind
__global__ __launch_bounds__(256, 2)
void edge_kernel(const float* __restrict__ u,
                 const float* __restrict__ v,
                 const float* __restrict__ edge_attr,
                 const float* __restrict__ W_e1, const float* __restrict__ b_e1,
                 const float* __restrict__ W_e2, const float* __restrict__ b_e2,
                 const float* __restrict__ W_c1, const float* __restrict__ b_c1,
                 const float* __restrict__ W_cl,
                 const int*   __restrict__ edge_index)
{
    extern __shared__ __align__(16) float smem[];
    float* sIn  = smem;                         // [ETILE][SI_STR]  w_diff + attr
    float* sPQ  = sIn + ETILE * SI_STR;         // [ETILE][SB_STR]  P[row]+Q[col], later feat
    float* sB   = sPQ + ETILE * SB_STR;         // [ETILE][SB_STR]  hid / c1
    int*   sRow = (int*)(sB + ETILE * SB_STR);  // [ETILE]
    float* sRad = (float*)(sRow + ETILE);       // [ETILE][2]

    const int tid = threadIdx.x;
    const int e0  = blockIdx.x * ETILE;

    // ---- gather P[row]+Q[col] (4 threads per edge, float4) ----
    {
        int e = tid >> 2, sub = tid & 3;
        int g = e0 + e;
        int r = edge_index[g];
        int c = edge_index[EE + g];
        const float4* Pr = (const float4*)(g_PQ + (size_t)r * 256);
        const float4* Qc = (const float4*)(g_PQ + (size_t)c * 256 + 128);
        float4* dst = (float4*)(sPQ + e * SB_STR);
        #pragma unroll
        for (int i = 0; i < 8; i++) {
            float4 a = Pr[sub + 4*i];
            float4 b = Qc[sub + 4*i];
            dst[sub + 4*i] = make_float4(a.x+b.x, a.y+b.y, a.z+b.z, a.w+b.w);
        }
        if (sub == 0) {
            sRow[e] = r;
            sIn[e * SI_STR + 33] = edge_attr[g];
            sIn[e * SI_STR + 34] = 0.f;
            sIn[e * SI_STR + 35] = 0.f;
            atomicAdd(&g_cnt[r], 1.0f);
        }
    }

    // ---- w_diff: rel_dirt / col_speed / row_speed ----
    for (int idx = tid; idx < ETILE * LVV; idx += 256) {
        int e = idx / LVV, lv = idx - e * LVV;
        int g = e0 + e;
        int r = edge_index[g], c = edge_index[EE + g];
        float ucv = u[c * LVV + lv], vcv = v[c * LVV + lv];
        float urv = u[r * LVV + lv], vrv = v[r * LVV + lv];
        float cs = sqrtf(ucv * ucv + vcv * vcv);
        float rs = sqrtf(urv * urv + vrv * vrv);
        float rd = (ucv * urv + vcv * vrv) / (cs * rs);
        float* rrow = sIn + e * SI_STR;
        rrow[0  + lv] = rd;
        rrow[11 + lv] = cs;
        rrow[22 + lv] = rs;
    }

    // ---- rad2 per edge ----
    for (int e = tid; e < ETILE; e += 256) {
        int g = e0 + e;
        int c = edge_index[EE + g];
        float su = 0.f, sv = 0.f;
        #pragma unroll
        for (int lv = 0; lv < LVV; lv++) {
            float a = u[c * LVV + lv], b = v[c * LVV + lv];
            su += a * a; sv += b * b;
        }
        sRad[e * 2 + 0] = sqrtf(su);
        sRad[e * 2 + 1] = sqrtf(sv);
    }
    __syncthreads();

    const int j  = tid & 127;
    const int eg = tid >> 7;

    // ---- GEMM1 (34-k): hid = relu(PQ + w_diff@W_e1[256:289] + attr*W_e1[289] + b_e1) ----
    {
        const float* W1w = W_e1 + 256 * HH;     // rows for w_diff + attr
        float bb = b_e1[j];
        float acc[32];
        const float* basePQ = sPQ + (eg * 32) * SB_STR;
        #pragma unroll
        for (int e = 0; e < 32; e++) acc[e] = basePQ[e * SB_STR + j] + bb;
        const float* base = sIn + (eg * 32) * SI_STR;
        for (int k = 0; k < 32; k += 4) {
            float w0 = W1w[(k+0)*HH + j], w1 = W1w[(k+1)*HH + j];
            float w2 = W1w[(k+2)*HH + j], w3 = W1w[(k+3)*HH + j];
            #pragma unroll
            for (int e = 0; e < 32; e++) {
                float4 a = *(const float4*)(base + e * SI_STR + k);
                acc[e] += a.x*w0 + a.y*w1 + a.z*w2 + a.w*w3;
            }
        }
        {   // tail k=32,33
            float w0 = W1w[32*HH + j], w1 = W1w[33*HH + j];
            #pragma unroll
            for (int e = 0; e < 32; e++) {
                const float* rr = base + e * SI_STR;
                acc[e] += rr[32]*w0 + rr[33]*w1;
            }
        }
        #pragma unroll
        for (int e = 0; e < 32; e++)
            sB[(eg*32 + e)*SB_STR + j] = fmaxf(acc[e], 0.f);
    }
    __syncthreads();

    // ---- GEMM2: feat = relu(hid @ W_e2 + b_e2) : sB -> sPQ ----
    {
        float acc[32];
        #pragma unroll
        for (int e = 0; e < 32; e++) acc[e] = 0.f;
        const float* base = sB + (eg * 32) * SB_STR;
        for (int k = 0; k < 128; k += 4) {
            float w0 = W_e2[(k+0)*HH + j], w1 = W_e2[(k+1)*HH + j];
            float w2 = W_e2[(k+2)*HH + j], w3 = W_e2[(k+3)*HH + j];
            #pragma unroll
            for (int e = 0; e < 32; e++) {
                float4 a = *(const float4*)(base + e * SB_STR + k);
                acc[e] += a.x*w0 + a.y*w1 + a.z*w2 + a.w*w3;
            }
        }
        float bb = b_e2[j];
        #pragma unroll
        for (int e = 0; e < 32; e++)
            sPQ[(eg*32 + e)*SB_STR + j] = fmaxf(acc[e] + bb, 0.f);
    }
    __syncthreads();

    // ---- scatter agg += feat (vector atomics) ----
    for (int idx = tid; idx < ETILE * 32; idx += 256) {
        int e = idx >> 5, q = idx & 31;
        float4 val = *(const float4*)(sPQ + e * SB_STR + q * 4);
        float* dst = g_agg + (size_t)sRow[e] * HH + q * 4;
        asm volatile("red.global.add.v4.f32 [%0], {%1,%2,%3,%4};"
                     :: "l"(dst), "f"(val.x), "f"(val.y), "f"(val.z), "f"(val.w)
                     : "memory");
    }

    // ---- coord GEMM1: c1 = relu(feat @ W_c1 + b_c1) : sPQ -> sB ----
    {
        float acc[32];
        #pragma unroll
        for (int e = 0; e < 32; e++) acc[e] = 0.f;
        const float* base = sPQ + (eg * 32) * SB_STR;
        for (int k = 0; k < 128; k += 4) {
            float w0 = W_c1[(k+0)*HH + j], w1 = W_c1[(k+1)*HH + j];
            float w2 = W_c1[(k+2)*HH + j], w3 = W_c1[(k+3)*HH + j];
            #pragma unroll
            for (int e = 0; e < 32; e++) {
                float4 a = *(const float4*)(base + e * SB_STR + k);
                acc[e] += a.x*w0 + a.y*w1 + a.z*w2 + a.w*w3;
            }
        }
        float bb = b_c1[j];
        #pragma unroll
        for (int e = 0; e < 32; e++)
            sB[(eg*32 + e)*SB_STR + j] = fmaxf(acc[e] + bb, 0.f);
    }
    __syncthreads();

    // ---- coord GEMM2 (H->22) * rad2, scatter wind ----
    for (int idx = tid; idx < ETILE * 22; idx += 256) {
        int e = idx / 22, m = idx - e * 22;
        const float* brow = sB + e * SB_STR;
        float acc = 0.f;
        #pragma unroll 8
        for (int k = 0; k < 128; k++)
            acc += brow[k] * W_cl[k * 22 + m];
        float r2 = sRad[e * 2 + (m >= 11 ? 1 : 0)];
        atomicAdd(&g_wind[(size_t)sRow[e] * 22 + m], acc * r2);
    }
}

// ============================================================
__global__ void lat_kernel() {
    int lt = blockIdx.x;          // 0..120
    int jj = threadIdx.x;         // 0..127
    float s = 0.f;
    for (int lon = 0; lon < NLON; lon++)
        s += g_agg[((size_t)lt * NLON + lon) * HH + jj];
    g_lat[lt * HH + jj] = s * (1.0f / NLON);
}

// ============================================================
// Node MLP: h_out = relu([h,agg,lat] @ W_n1 + b_n1) @ W_n2 + b_n2 + h
__global__ __launch_bounds__(256, 3)
void node_kernel(const float* __restrict__ h,
                 const float* __restrict__ W_n1, const float* __restrict__ b_n1,
                 const float* __restrict__ W_n2, const float* __restrict__ b_n2,
                 float* __restrict__ out)
{
    extern __shared__ __align__(16) float smem[];
    float* sA = smem;                  // [NTILE][NA_STR]
    float* sB = sA + NTILE * NA_STR;   // [NTILE][SB_STR]

    const int tid = threadIdx.x;
    const int n0  = blockIdx.x * NTILE;

    {
        int e = tid >> 3, sub = tid & 7;   // 32 rows x 8 threads
        int n = n0 + e;
        float4* dst = (float4*)(sA + e * NA_STR);
        if (n < NN) {
            const float4* hh = (const float4*)(h + (size_t)n * HH);
            const float4* aa = (const float4*)(g_agg + (size_t)n * HH);
            const float4* ll = (const float4*)(g_lat + (size_t)(n / NLON) * HH);
            #pragma unroll
            for (int i = 0; i < 4; i++) {
                dst[sub + 8*i]      = hh[sub + 8*i];
                dst[32 + sub + 8*i] = aa[sub + 8*i];
                dst[64 + sub + 8*i] = ll[sub + 8*i];
            }
        } else {
            float4 z = make_float4(0.f, 0.f, 0.f, 0.f);
            #pragma unroll
            for (int i = 0; i < 4; i++) {
                dst[sub + 8*i] = z; dst[32 + sub + 8*i] = z; dst[64 + sub + 8*i] = z;
            }
        }
    }
    __syncthreads();

    const int j  = tid & 127;
    const int eg = tid >> 7;           // 0/1, 16 rows each

    // GEMM1: [32,384]@[384,128], relu -> sB
    {
        float acc[16];
        #pragma unroll
        for (int e = 0; e < 16; e++) acc[e] = 0.f;
        const float* base = sA + (eg * 16) * NA_STR;
        for (int k = 0; k < NA_STR; k += 4) {
            float w0 = W_n1[(k+0)*HH + j], w1 = W_n1[(k+1)*HH + j];
            float w2 = W_n1[(k+2)*HH + j], w3 = W_n1[(k+3)*HH + j];
            #pragma unroll
            for (int e = 0; e < 16; e++) {
                float4 a = *(const float4*)(base + e * NA_STR + k);
                acc[e] += a.x*w0 + a.y*w1 + a.z*w2 + a.w*w3;
            }
        }
        float bb = b_n1[j];
        #pragma unroll
        for (int e = 0; e < 16; e++)
            sB[(eg*16 + e)*SB_STR + j] = fmaxf(acc[e] + bb, 0.f);
    }
    __syncthreads();

    // GEMM2: [32,128]@[128,128] + b + residual -> out
    {
        float acc[16];
        #pragma unroll
        for (int e = 0; e < 16; e++) acc[e] = 0.f;
        const float* base = sB + (eg * 16) * SB_STR;
        for (int k = 0; k < 128; k += 4) {
            float w0 = W_n2[(k+0)*HH + j], w1 = W_n2[(k+1)*HH + j];
            float w2 = W_n2[(k+2)*HH + j], w3 = W_n2[(k+3)*HH + j];
            #pragma unroll
            for (int e = 0; e < 16; e++) {
                float4 a = *(const float4*)(base + e * SB_STR + k);
                acc[e] += a.x*w0 + a.y*w1 + a.z*w2 + a.w*w3;
            }
        }
        float bb = b_n2[j];
        #pragma unroll
        for (int e = 0; e < 16; e++) {
            int n = n0 + eg*16 + e;
            if (n < NN)
                out[(size_t)n * HH + j] = acc[e] + bb + h[(size_t)n * HH + j];
        }
    }
}

// ============================================================
__global__ void coord_kernel(float* __restrict__ out) {
    int i = blockIdx.x * 256 + threadIdx.x;     // over NN*22
    if (i >= NN * 22) return;
    int n = i / 22, m = i - n * 22;
    float cnt = fmaxf(g_cnt[n], 1.0f);
    float val = g_wind[i] / cnt;
    val = fminf(fmaxf(val, -100.0f), 100.0f);
    int lv = (m >= 11) ? (m - 11) : m;
    float* o = out + (size_t)NN * HH + (m >= 11 ? NN * LVV : 0) + n * LVV + lv;
    *o = val;
}

// ============================================================
extern "C" void kernel_launch(void* const* d_in, const int* in_sizes, int n_in,
                              void* d_out, int out_size)
{
    const float* h         = (const float*)d_in[0];
    const float* u         = (const float*)d_in[1];
    const float* v         = (const float*)d_in[2];
    const float* edge_attr = (const float*)d_in[3];
    const float* W_e1      = (const float*)d_in[4];
    const float* b_e1      = (const float*)d_in[5];
    const float* W_e2      = (const float*)d_in[6];
    const float* b_e2      = (const float*)d_in[7];
    const float* W_n1      = (const float*)d_in[8];
    const float* b_n1      = (const float*)d_in[9];
    const float* W_n2      = (const float*)d_in[10];
    const float* b_n2      = (const float*)d_in[11];
    const float* W_c1      = (const float*)d_in[12];
    const float* b_c1      = (const float*)d_in[13];
    const float* W_cl      = (const float*)d_in[14];
    const int*   edge_index= (const int*)  d_in[15];
    float* out = (float*)d_out;

    const int PQ_SMEM   = 64 * SB_STR * 4;
    const int EDGE_SMEM = (ETILE * SI_STR + 2 * ETILE * SB_STR) * 4 + ETILE * 4 + ETILE * 2 * 4;
    const int NODE_SMEM = (NTILE * NA_STR + NTILE * SB_STR) * 4;
    cudaFuncSetAttribute(pq_kernel,   cudaFuncAttributeMaxDynamicSharedMemorySize, PQ_SMEM);
    cudaFuncSetAttribute(edge_kernel, cudaFuncAttributeMaxDynamicSharedMemorySize, EDGE_SMEM);
    cudaFuncSetAttribute(node_kernel, cudaFuncAttributeMaxDynamicSharedMemorySize, NODE_SMEM);

    zero_kernel<<<(NN * HH + 255) / 256, 256>>>();

    pq_kernel<<<(NN + 63) / 64, 256, PQ_SMEM>>>(h, W_e1);

    edge_kernel<<<EE / ETILE, 256, EDGE_SMEM>>>(u, v, edge_attr,
                                                W_e1, b_e1, W_e2, b_e2,
                                                W_c1, b_c1, W_cl, edge_index);

    lat_kernel<<<NLAT, HH>>>();

    node_kernel<<<(NN + NTILE - 1) / NTILE, 256, NODE_SMEM>>>(h, W_n1, b_n1, W_n2, b_n2, out);

    coord_kernel<<<(NN * 22 + 255) / 256, 256>>>(out);
}

// round 5
// speedup vs baseline: 1.6090x; 1.0291x over previous
#include <cuda_runtime.h>
#include <cuda_bf16.h>
#include <cstdint>

// Problem constants
#define NN      29040        // nodes (121*240)
#define EE      464640       // edges (NN*16)
#define HH      128          // hidden
#define LVV     11           // levels
#define NLAT    121
#define NLON    240

// Edge kernel tiling
#define ETILE   64
#define SI_STR  36           // w_diff(33)+attr(1), padded
#define SB_STR  132          // padded 128

// Node kernel tiling
#define NTILE   32
#define NA_STR  384          // 3*H

typedef unsigned long long u64;

// ---- packed f32x2 helpers (sm_100a Blackwell family) ----
__device__ __forceinline__ u64 pk2(float lo, float hi) {
    u64 r; asm("mov.b64 %0, {%1,%2};" : "=l"(r) : "f"(lo), "f"(hi)); return r;
}
__device__ __forceinline__ void ffma2(u64& acc, u64 a, u64 b) {
    asm("fma.rn.f32x2 %0, %1, %2, %0;" : "+l"(acc) : "l"(a), "l"(b));
}
__device__ __forceinline__ float hadd2(u64 x) {
    float lo, hi; asm("mov.b64 {%0,%1}, %2;" : "=f"(lo), "=f"(hi) : "l"(x));
    return lo + hi;
}

// ---- scratch (no allocation allowed) ----
__device__ float g_agg[NN * HH];      // scatter-sum of edge_feat
__device__ float g_wind[NN * 22];     // scatter-sum of wind
__device__ float g_cnt[NN];           // edges per row
__device__ float g_lat[NLAT * HH];    // lat-band means
__device__ float g_PQ[NN * 256];      // P at [n][0:128], Q at [n][128:256]

// ============================================================
__global__ void zero_kernel() {
    int i = blockIdx.x * 256 + threadIdx.x;
    if (i < NN * HH) g_agg[i] = 0.f;
    if (i < NN * 22) g_wind[i] = 0.f;
    if (i < NN)      g_cnt[i] = 0.f;
}

// ============================================================
// Precompute P = h @ W_e1[0:128,:], Q = h @ W_e1[128:256,:]
__global__ __launch_bounds__(256, 2)
void pq_kernel(const float* __restrict__ h,
               const float* __restrict__ W_e1)
{
    extern __shared__ __align__(16) float smem[];
    float* sH = smem;                  // [64][SB_STR]

    const int tid = threadIdx.x;
    const int n0  = blockIdx.x * 64;

    {   // gather 64 rows of h (coalesced)
        int e = tid >> 2, sub = tid & 3;
        int n = n0 + e;
        float4* dst = (float4*)(sH + e * SB_STR);
        if (n < NN) {
            const float4* hh = (const float4*)(h + (size_t)n * HH);
            #pragma unroll
            for (int i = 0; i < 8; i++) dst[sub + 4*i] = hh[sub + 4*i];
        } else {
            float4 z = make_float4(0.f,0.f,0.f,0.f);
            #pragma unroll
            for (int i = 0; i < 8; i++) dst[sub + 4*i] = z;
        }
    }
    __syncthreads();

    const int j  = tid & 127;
    const int eg = tid >> 7;

    #pragma unroll
    for (int half = 0; half < 2; half++) {
        const float* W = W_e1 + half * 128 * HH;
        u64 acc[32];
        #pragma unroll
        for (int e = 0; e < 32; e++) acc[e] = 0ULL;
        const float* base = sH + (eg * 32) * SB_STR;
        for (int k = 0; k < 128; k += 4) {
            u64 W01 = pk2(W[(k+0)*HH + j], W[(k+1)*HH + j]);
            u64 W23 = pk2(W[(k+2)*HH + j], W[(k+3)*HH + j]);
            #pragma unroll
            for (int e = 0; e < 32; e++) {
                ulonglong2 a = *(const ulonglong2*)(base + e * SB_STR + k);
                ffma2(acc[e], a.x, W01);
                ffma2(acc[e], a.y, W23);
            }
        }
        #pragma unroll
        for (int e = 0; e < 32; e++) {
            int n = n0 + eg*32 + e;
            if (n < NN) g_PQ[(size_t)n * 256 + half * 128 + j] = hadd2(acc[e]);
        }
    }
}

// ============================================================
// Fused edge pass
__global__ __launch_bounds__(256, 2)
void edge_kernel(const float* __restrict__ u,
                 const float* __restrict__ v,
                 const float* __restrict__ edge_attr,
                 const float* __restrict__ W_e1, const float* __restrict__ b_e1,
                 const float* __restrict__ W_e2, const float* __restrict__ b_e2,
                 const float* __restrict__ W_c1, const float* __restrict__ b_c1,
                 const float* __restrict__ W_cl,
                 const int*   __restrict__ edge_index)
{
    extern __shared__ __align__(16) float smem[];
    float* sIn  = smem;                         // [ETILE][SI_STR]  w_diff + attr
    float* sPQ  = sIn + ETILE * SI_STR;         // [ETILE][SB_STR]  P[row]+Q[col], later feat
    float* sB   = sPQ + ETILE * SB_STR;         // [ETILE][SB_STR]  hid / c1
    int*   sRow = (int*)(sB + ETILE * SB_STR);  // [ETILE]
    float* sRad = (float*)(sRow + ETILE);       // [ETILE][2]
    u64*   sWcl = (u64*)(sRad + ETILE * 2);     // [64][22] packed W_cl k-pairs

    const int tid = threadIdx.x;
    const int e0  = blockIdx.x * ETILE;

    // ---- pack W_cl k-pairs into shared: sWcl[kk*22+m] = {W_cl[2kk][m], W_cl[2kk+1][m]} ----
    for (int idx = tid; idx < 64 * 22; idx += 256) {
        int kk = idx / 22, m = idx - kk * 22;
        sWcl[idx] = pk2(W_cl[(2*kk) * 22 + m], W_cl[(2*kk+1) * 22 + m]);
    }

    // ---- gather P[row]+Q[col] (4 threads per edge, float4) ----
    {
        int e = tid >> 2, sub = tid & 3;
        int g = e0 + e;
        int r = edge_index[g];
        int c = edge_index[EE + g];
        const float4* Pr = (const float4*)(g_PQ + (size_t)r * 256);
        const float4* Qc = (const float4*)(g_PQ + (size_t)c * 256 + 128);
        float4* dst = (float4*)(sPQ + e * SB_STR);
        #pragma unroll
        for (int i = 0; i < 8; i++) {
            float4 a = Pr[sub + 4*i];
            float4 b = Qc[sub + 4*i];
            dst[sub + 4*i] = make_float4(a.x+b.x, a.y+b.y, a.z+b.z, a.w+b.w);
        }
        if (sub == 0) {
            sRow[e] = r;
            sIn[e * SI_STR + 33] = edge_attr[g];
            sIn[e * SI_STR + 34] = 0.f;
            sIn[e * SI_STR + 35] = 0.f;
            atomicAdd(&g_cnt[r], 1.0f);
        }
    }

    // ---- w_diff ----
    for (int idx = tid; idx < ETILE * LVV; idx += 256) {
        int e = idx / LVV, lv = idx - e * LVV;
        int g = e0 + e;
        int r = edge_index[g], c = edge_index[EE + g];
        float ucv = u[c * LVV + lv], vcv = v[c * LVV + lv];
        float urv = u[r * LVV + lv], vrv = v[r * LVV + lv];
        float cs = sqrtf(ucv * ucv + vcv * vcv);
        float rs = sqrtf(urv * urv + vrv * vrv);
        float rd = (ucv * urv + vcv * vrv) / (cs * rs);
        float* rrow = sIn + e * SI_STR;
        rrow[0  + lv] = rd;
        rrow[11 + lv] = cs;
        rrow[22 + lv] = rs;
    }

    // ---- rad2 per edge ----
    for (int e = tid; e < ETILE; e += 256) {
        int g = e0 + e;
        int c = edge_index[EE + g];
        float su = 0.f, sv = 0.f;
        #pragma unroll
        for (int lv = 0; lv < LVV; lv++) {
            float a = u[c * LVV + lv], b = v[c * LVV + lv];
            su += a * a; sv += b * b;
        }
        sRad[e * 2 + 0] = sqrtf(su);
        sRad[e * 2 + 1] = sqrtf(sv);
    }
    __syncthreads();

    const int j  = tid & 127;
    const int eg = tid >> 7;

    // ---- GEMM1 (34-k): hid = relu(PQ + w_diff@W_e1[256:289] + attr*W_e1[289] + b_e1) ----
    {
        const float* W1w = W_e1 + 256 * HH;
        float bb = b_e1[j];
        u64 acc[32];
        const float* basePQ = sPQ + (eg * 32) * SB_STR;
        #pragma unroll
        for (int e = 0; e < 32; e++) acc[e] = pk2(basePQ[e * SB_STR + j] + bb, 0.f);
        const float* base = sIn + (eg * 32) * SI_STR;
        for (int k = 0; k < 32; k += 4) {
            u64 W01 = pk2(W1w[(k+0)*HH + j], W1w[(k+1)*HH + j]);
            u64 W23 = pk2(W1w[(k+2)*HH + j], W1w[(k+3)*HH + j]);
            #pragma unroll
            for (int e = 0; e < 32; e++) {
                ulonglong2 a = *(const ulonglong2*)(base + e * SI_STR + k);
                ffma2(acc[e], a.x, W01);
                ffma2(acc[e], a.y, W23);
            }
        }
        {   // tail k=32,33 (one pair)
            u64 Wt = pk2(W1w[32*HH + j], W1w[33*HH + j]);
            #pragma unroll
            for (int e = 0; e < 32; e++) {
                u64 a = *(const u64*)(base + e * SI_STR + 32);
                ffma2(acc[e], a, Wt);
            }
        }
        #pragma unroll
        for (int e = 0; e < 32; e++)
            sB[(eg*32 + e)*SB_STR + j] = fmaxf(hadd2(acc[e]), 0.f);
    }
    __syncthreads();

    // ---- GEMM2: feat = relu(hid @ W_e2 + b_e2) : sB -> sPQ ----
    {
        u64 acc[32];
        #pragma unroll
        for (int e = 0; e < 32; e++) acc[e] = 0ULL;
        const float* base = sB + (eg * 32) * SB_STR;
        for (int k = 0; k < 128; k += 4) {
            u64 W01 = pk2(W_e2[(k+0)*HH + j], W_e2[(k+1)*HH + j]);
            u64 W23 = pk2(W_e2[(k+2)*HH + j], W_e2[(k+3)*HH + j]);
            #pragma unroll
            for (int e = 0; e < 32; e++) {
                ulonglong2 a = *(const ulonglong2*)(base + e * SB_STR + k);
                ffma2(acc[e], a.x, W01);
                ffma2(acc[e], a.y, W23);
            }
        }
        float bb = b_e2[j];
        #pragma unroll
        for (int e = 0; e < 32; e++)
            sPQ[(eg*32 + e)*SB_STR + j] = fmaxf(hadd2(acc[e]) + bb, 0.f);
    }
    __syncthreads();

    // ---- scatter agg += feat (vector atomics) ----
    for (int idx = tid; idx < ETILE * 32; idx += 256) {
        int e = idx >> 5, q = idx & 31;
        float4 val = *(const float4*)(sPQ + e * SB_STR + q * 4);
        float* dst = g_agg + (size_t)sRow[e] * HH + q * 4;
        asm volatile("red.global.add.v4.f32 [%0], {%1,%2,%3,%4};"
                     :: "l"(dst), "f"(val.x), "f"(val.y), "f"(val.z), "f"(val.w)
                     : "memory");
    }

    // ---- coord GEMM1: c1 = relu(feat @ W_c1 + b_c1) : sPQ -> sB ----
    {
        u64 acc[32];
        #pragma unroll
        for (int e = 0; e < 32; e++) acc[e] = 0ULL;
        const float* base = sPQ + (eg * 32) * SB_STR;
        for (int k = 0; k < 128; k += 4) {
            u64 W01 = pk2(W_c1[(k+0)*HH + j], W_c1[(k+1)*HH + j]);
            u64 W23 = pk2(W_c1[(k+2)*HH + j], W_c1[(k+3)*HH + j]);
            #pragma unroll
            for (int e = 0; e < 32; e++) {
                ulonglong2 a = *(const ulonglong2*)(base + e * SB_STR + k);
                ffma2(acc[e], a.x, W01);
                ffma2(acc[e], a.y, W23);
            }
        }
        float bb = b_c1[j];
        #pragma unroll
        for (int e = 0; e < 32; e++)
            sB[(eg*32 + e)*SB_STR + j] = fmaxf(hadd2(acc[e]) + bb, 0.f);
    }
    __syncthreads();

    // ---- coord GEMM2 (H->22) * rad2, scatter wind (packed pairs) ----
    for (int idx = tid; idx < ETILE * 22; idx += 256) {
        int e = idx / 22, m = idx - e * 22;
        const u64* brow = (const u64*)(sB + e * SB_STR);   // 64 k-pairs
        u64 acc = 0ULL;
        #pragma unroll 8
        for (int kk = 0; kk < 64; kk++)
            ffma2(acc, brow[kk], sWcl[kk * 22 + m]);
        float r2 = sRad[e * 2 + (m >= 11 ? 1 : 0)];
        atomicAdd(&g_wind[(size_t)sRow[e] * 22 + m], hadd2(acc) * r2);
    }
}

// ============================================================
__global__ void lat_kernel() {
    int lt = blockIdx.x;          // 0..120
    int jj = threadIdx.x;         // 0..127
    float s = 0.f;
    for (int lon = 0; lon < NLON; lon++)
        s += g_agg[((size_t)lt * NLON + lon) * HH + jj];
    g_lat[lt * HH + jj] = s * (1.0f / NLON);
}

// ============================================================
// Node MLP: h_out = relu([h,agg,lat] @ W_n1 + b_n1) @ W_n2 + b_n2 + h
__global__ __launch_bounds__(256, 3)
void node_kernel(const float* __restrict__ h,
                 const float* __restrict__ W_n1, const float* __restrict__ b_n1,
                 const float* __restrict__ W_n2, const float* __restrict__ b_n2,
                 float* __restrict__ out)
{
    extern __shared__ __align__(16) float smem[];
    float* sA = smem;                  // [NTILE][NA_STR]
    float* sB = sA + NTILE * NA_STR;   // [NTILE][SB_STR]

    const int tid = threadIdx.x;
    const int n0  = blockIdx.x * NTILE;

    {
        int e = tid >> 3, sub = tid & 7;   // 32 rows x 8 threads
        int n = n0 + e;
        float4* dst = (float4*)(sA + e * NA_STR);
        if (n < NN) {
            const float4* hh = (const float4*)(h + (size_t)n * HH);
            const float4* aa = (const float4*)(g_agg + (size_t)n * HH);
            const float4* ll = (const float4*)(g_lat + (size_t)(n / NLON) * HH);
            #pragma unroll
            for (int i = 0; i < 4; i++) {
                dst[sub + 8*i]      = hh[sub + 8*i];
                dst[32 + sub + 8*i] = aa[sub + 8*i];
                dst[64 + sub + 8*i] = ll[sub + 8*i];
            }
        } else {
            float4 z = make_float4(0.f, 0.f, 0.f, 0.f);
            #pragma unroll
            for (int i = 0; i < 4; i++) {
                dst[sub + 8*i] = z; dst[32 + sub + 8*i] = z; dst[64 + sub + 8*i] = z;
            }
        }
    }
    __syncthreads();

    const int j  = tid & 127;
    const int eg = tid >> 7;           // 0/1, 16 rows each

    // GEMM1: [32,384]@[384,128], relu -> sB
    {
        u64 acc[16];
        #pragma unroll
        for (int e = 0; e < 16; e++) acc[e] = 0ULL;
        const float* base = sA + (eg * 16) * NA_STR;
        for (int k = 0; k < NA_STR; k += 4) {
            u64 W01 = pk2(W_n1[(k+0)*HH + j], W_n1[(k+1)*HH + j]);
            u64 W23 = pk2(W_n1[(k+2)*HH + j], W_n1[(k+3)*HH + j]);
            #pragma unroll
            for (int e = 0; e < 16; e++) {
                ulonglong2 a = *(const ulonglong2*)(base + e * NA_STR + k);
                ffma2(acc[e], a.x, W01);
                ffma2(acc[e], a.y, W23);
            }
        }
        float bb = b_n1[j];
        #pragma unroll
        for (int e = 0; e < 16; e++)
            sB[(eg*16 + e)*SB_STR + j] = fmaxf(hadd2(acc[e]) + bb, 0.f);
    }
    __syncthreads();

    // GEMM2: [32,128]@[128,128] + b + residual -> out
    {
        u64 acc[16];
        #pragma unroll
        for (int e = 0; e < 16; e++) acc[e] = 0ULL;
        const float* base = sB + (eg * 16) * SB_STR;
        for (int k = 0; k < 128; k += 4) {
            u64 W01 = pk2(W_n2[(k+0)*HH + j], W_n2[(k+1)*HH + j]);
            u64 W23 = pk2(W_n2[(k+2)*HH + j], W_n2[(k+3)*HH + j]);
            #pragma unroll
            for (int e = 0; e < 16; e++) {
                ulonglong2 a = *(const ulonglong2*)(base + e * SB_STR + k);
                ffma2(acc[e], a.x, W01);
                ffma2(acc[e], a.y, W23);
            }
        }
        float bb = b_n2[j];
        #pragma unroll
        for (int e = 0; e < 16; e++) {
            int n = n0 + eg*16 + e;
            if (n < NN)
                out[(size_t)n * HH + j] = hadd2(acc[e]) + bb + h[(size_t)n * HH + j];
        }
    }
}

// ============================================================
__global__ void coord_kernel(float* __restrict__ out) {
    int i = blockIdx.x * 256 + threadIdx.x;     // over NN*22
    if (i >= NN * 22) return;
    int n = i / 22, m = i - n * 22;
    float cnt = fmaxf(g_cnt[n], 1.0f);
    float val = g_wind[i] / cnt;
    val = fminf(fmaxf(val, -100.0f), 100.0f);
    int lv = (m >= 11) ? (m - 11) : m;
    float* o = out + (size_t)NN * HH + (m >= 11 ? NN * LVV : 0) + n * LVV + lv;
    *o = val;
}

// ============================================================
extern "C" void kernel_launch(void* const* d_in, const int* in_sizes, int n_in,
                              void* d_out, int out_size)
{
    const float* h         = (const float*)d_in[0];
    const float* u         = (const float*)d_in[1];
    const float* v         = (const float*)d_in[2];
    const float* edge_attr = (const float*)d_in[3];
    const float* W_e1      = (const float*)d_in[4];
    const float* b_e1      = (const float*)d_in[5];
    const float* W_e2      = (const float*)d_in[6];
    const float* b_e2      = (const float*)d_in[7];
    const float* W_n1      = (const float*)d_in[8];
    const float* b_n1      = (const float*)d_in[9];
    const float* W_n2      = (const float*)d_in[10];
    const float* b_n2      = (const float*)d_in[11];
    const float* W_c1      = (const float*)d_in[12];
    const float* b_c1      = (const float*)d_in[13];
    const float* W_cl      = (const float*)d_in[14];
    const int*   edge_index= (const int*)  d_in[15];
    float* out = (float*)d_out;

    const int PQ_SMEM   = 64 * SB_STR * 4;
    const int EDGE_SMEM = (ETILE * SI_STR + 2 * ETILE * SB_STR) * 4
                        + ETILE * 4 + ETILE * 2 * 4
                        + 64 * 22 * 8;                       // sWcl packed pairs
    const int NODE_SMEM = (NTILE * NA_STR + NTILE * SB_STR) * 4;
    cudaFuncSetAttribute(pq_kernel,   cudaFuncAttributeMaxDynamicSharedMemorySize, PQ_SMEM);
    cudaFuncSetAttribute(edge_kernel, cudaFuncAttributeMaxDynamicSharedMemorySize, EDGE_SMEM);
    cudaFuncSetAttribute(node_kernel, cudaFuncAttributeMaxDynamicSharedMemorySize, NODE_SMEM);

    zero_kernel<<<(NN * HH + 255) / 256, 256>>>();

    pq_kernel<<<(NN + 63) / 64, 256, PQ_SMEM>>>(h, W_e1);

    edge_kernel<<<EE / ETILE, 256, EDGE_SMEM>>>(u, v, edge_attr,
                                                W_e1, b_e1, W_e2, b_e2,
                                                W_c1, b_c1, W_cl, edge_index);

    lat_kernel<<<NLAT, HH>>>();

    node_kernel<<<(NN + NTILE - 1) / NTILE, 256, NODE_SMEM>>>(h, W_n1, b_n1, W_n2, b_n2, out);

    coord_kernel<<<(NN * 22 + 255) / 256, 256>>>(out);
}

// round 6
// speedup vs baseline: 1.6310x; 1.0137x over previous
#include <cuda_runtime.h>
#include <cuda_bf16.h>
#include <cstdint>

// Problem constants
#define NN      29040        // nodes (121*240)
#define EE      464640       // edges (NN*16)
#define HH      128          // hidden
#define LVV     11           // levels
#define NLAT    121
#define NLON    240

// Edge kernel tiling
#define ETILE   64
#define SI_STR  36           // w_diff(33)+attr(1), padded
#define SB_STR  132          // padded 128 (fp32 buffers)
#define AK      136          // bf16 activation row stride (128 + 8 pad)
#define WK      136          // bf16 weight row stride

// Node kernel tiling
#define NTILE   32
#define NA_STR  384          // 3*H

typedef unsigned long long u64;

// ---- packed f32x2 helpers (kept from measured kernel; harmless on sm_100a) ----
__device__ __forceinline__ u64 pk2(float lo, float hi) {
    u64 r; asm("mov.b64 %0, {%1,%2};" : "=l"(r) : "f"(lo), "f"(hi)); return r;
}
__device__ __forceinline__ void ffma2(u64& acc, u64 a, u64 b) {
    asm("fma.rn.f32x2 %0, %1, %2, %0;" : "+l"(acc) : "l"(a), "l"(b));
}
__device__ __forceinline__ float hadd2(u64 x) {
    float lo, hi; asm("mov.b64 {%0,%1}, %2;" : "=f"(lo), "=f"(hi) : "l"(x));
    return lo + hi;
}

// ---- bf16 split helpers ----
__device__ __forceinline__ void bf16split(float x, __nv_bfloat16& hi, __nv_bfloat16& lo) {
    hi = __float2bfloat16_rn(x);
    lo = __float2bfloat16_rn(x - __bfloat162float(hi));
}

// ---- m16n8k16 bf16 MMA ----
__device__ __forceinline__ void mma16816(float* c,
    uint32_t a0, uint32_t a1, uint32_t a2, uint32_t a3,
    uint32_t b0, uint32_t b1)
{
    asm volatile(
        "mma.sync.aligned.m16n8k16.row.col.f32.bf16.bf16.f32 "
        "{%0,%1,%2,%3}, {%4,%5,%6,%7}, {%8,%9}, {%0,%1,%2,%3};"
        : "+f"(c[0]), "+f"(c[1]), "+f"(c[2]), "+f"(c[3])
        : "r"(a0), "r"(a1), "r"(a2), "r"(a3), "r"(b0), "r"(b1));
}

// ---- scratch (no allocation allowed) ----
__device__ float g_agg[NN * HH];      // scatter-sum of edge_feat
__device__ float g_wind[NN * 22];     // scatter-sum of wind
__device__ float g_cnt[NN];           // edges per row
__device__ float g_lat[NLAT * HH];    // lat-band means
__device__ float g_PQ[NN * 256];      // P at [n][0:128], Q at [n][128:256]

// ---- edge-kernel SMEM layout (byte offsets) ----
#define OFF_PQ   0                                   // [64][132] f32  feat / PQ
#define OFF_B    (OFF_PQ  + ETILE*SB_STR*4)          // [64][132] f32  hid / c1
#define OFF_IN   (OFF_B   + ETILE*SB_STR*4)          // [64][36]  f32  w_diff+attr
#define OFF_ROW  (OFF_IN  + ETILE*SI_STR*4)          // [64] int
#define OFF_RAD  (OFF_ROW + ETILE*4)                 // [64][2] f32
#define OFF_WCL  (OFF_RAD + ETILE*2*4)               // [64][22] u64 packed W_cl
#define OFF_AHI  (OFF_WCL + 64*22*8)                 // [64][AK] bf16
#define OFF_ALO  (OFF_AHI + ETILE*AK*2)
#define OFF_WHI  (OFF_ALO + ETILE*AK*2)              // [128][WK] bf16 (B in [n][k])
#define OFF_WLO  (OFF_WHI + HH*WK*2)
#define EDGE_SMEM (OFF_WLO + HH*WK*2)                // = 193280 bytes

// ============================================================
__global__ void zero_kernel() {
    int i = blockIdx.x * 256 + threadIdx.x;
    if (i < NN * HH) g_agg[i] = 0.f;
    if (i < NN * 22) g_wind[i] = 0.f;
    if (i < NN)      g_cnt[i] = 0.f;
}

// ============================================================
// Precompute P = h @ W_e1[0:128,:], Q = h @ W_e1[128:256,:]
__global__ __launch_bounds__(256, 2)
void pq_kernel(const float* __restrict__ h,
               const float* __restrict__ W_e1)
{
    extern __shared__ __align__(16) float smemf[];
    float* sH = smemf;                 // [64][SB_STR]

    const int tid = threadIdx.x;
    const int n0  = blockIdx.x * 64;

    {   // gather 64 rows of h (coalesced)
        int e = tid >> 2, sub = tid & 3;
        int n = n0 + e;
        float4* dst = (float4*)(sH + e * SB_STR);
        if (n < NN) {
            const float4* hh = (const float4*)(h + (size_t)n * HH);
            #pragma unroll
            for (int i = 0; i < 8; i++) dst[sub + 4*i] = hh[sub + 4*i];
        } else {
            float4 z = make_float4(0.f,0.f,0.f,0.f);
            #pragma unroll
            for (int i = 0; i < 8; i++) dst[sub + 4*i] = z;
        }
    }
    __syncthreads();

    const int j  = tid & 127;
    const int eg = tid >> 7;

    #pragma unroll
    for (int half = 0; half < 2; half++) {
        const float* W = W_e1 + half * 128 * HH;
        u64 acc[32];
        #pragma unroll
        for (int e = 0; e < 32; e++) acc[e] = 0ULL;
        const float* base = sH + (eg * 32) * SB_STR;
        for (int k = 0; k < 128; k += 4) {
            u64 W01 = pk2(W[(k+0)*HH + j], W[(k+1)*HH + j]);
            u64 W23 = pk2(W[(k+2)*HH + j], W[(k+3)*HH + j]);
            #pragma unroll
            for (int e = 0; e < 32; e++) {
                ulonglong2 a = *(const ulonglong2*)(base + e * SB_STR + k);
                ffma2(acc[e], a.x, W01);
                ffma2(acc[e], a.y, W23);
            }
        }
        #pragma unroll
        for (int e = 0; e < 32; e++) {
            int n = n0 + eg*32 + e;
            if (n < NN) g_PQ[(size_t)n * 256 + half * 128 + j] = hadd2(acc[e]);
        }
    }
}

// ============================================================
// MMA helpers for the edge kernel

// Split a [128][128] row-major fp32 weight (k-major rows) into bf16 hi/lo
// stored transposed [n][k] (k contiguous) -> col-major B operand.
__device__ __forceinline__ void split_weight(const float* __restrict__ W,
                                             __nv_bfloat16* sWhi,
                                             __nv_bfloat16* sWlo, int tid)
{
    for (int idx = tid; idx < 128 * 128; idx += 256) {
        int k = idx >> 7, n = idx & 127;
        float x = W[idx];
        __nv_bfloat16 hi, lo; bf16split(x, hi, lo);
        sWhi[n * WK + k] = hi;
        sWlo[n * WK + k] = lo;
    }
}

// Split [64][128] fp32 activations (stride srcStride) into bf16 hi/lo row-major.
__device__ __forceinline__ void split_act(const float* __restrict__ src, int srcStride,
                                          __nv_bfloat16* sAhi,
                                          __nv_bfloat16* sAlo, int tid)
{
    for (int idx = tid; idx < 64 * 128; idx += 256) {
        int e = idx >> 7, k = idx & 127;
        float x = src[e * srcStride + k];
        __nv_bfloat16 hi, lo; bf16split(x, hi, lo);
        sAhi[e * AK + k] = hi;
        sAlo[e * AK + k] = lo;
    }
}

// D[64][128] = relu( A[64][128] @ W[128][128] + bias )  via split-bf16 MMA.
// A in sAhi/sAlo (row-major, stride AK), W in sWhi/sWlo ([n][k], stride WK).
__device__ __forceinline__ void mma_gemm_relu(
    const __nv_bfloat16* __restrict__ sAhi, const __nv_bfloat16* __restrict__ sAlo,
    const __nv_bfloat16* __restrict__ sWhi, const __nv_bfloat16* __restrict__ sWlo,
    const float* __restrict__ bias, float* __restrict__ dst, int tid)
{
    const int w = tid >> 5, lane = tid & 31;
    const int g = lane >> 2, tig = lane & 3;
    const int m0 = (w & 3) * 16;          // 4 m-blocks of 16 rows
    const int nbase = (w >> 2) * 64;      // 2 n-halves of 64 cols

    float acc[32];
    #pragma unroll
    for (int i = 0; i < 32; i++) acc[i] = 0.f;

    #pragma unroll
    for (int kb = 0; kb < 8; kb++) {
        const int k0 = kb * 16;
        const int ar = (m0 + g) * AK + k0 + 2 * tig;
        uint32_t ah0 = *(const uint32_t*)(sAhi + ar);
        uint32_t ah1 = *(const uint32_t*)(sAhi + ar + 8 * AK);
        uint32_t ah2 = *(const uint32_t*)(sAhi + ar + 8);
        uint32_t ah3 = *(const uint32_t*)(sAhi + ar + 8 * AK + 8);
        uint32_t al0 = *(const uint32_t*)(sAlo + ar);
        uint32_t al1 = *(const uint32_t*)(sAlo + ar + 8 * AK);
        uint32_t al2 = *(const uint32_t*)(sAlo + ar + 8);
        uint32_t al3 = *(const uint32_t*)(sAlo + ar + 8 * AK + 8);
        #pragma unroll
        for (int nb = 0; nb < 8; nb++) {
            const int n0 = nbase + nb * 8;
            const int br = (n0 + g) * WK + k0 + 2 * tig;
            uint32_t bh0 = *(const uint32_t*)(sWhi + br);
            uint32_t bh1 = *(const uint32_t*)(sWhi + br + 8);
            uint32_t bl0 = *(const uint32_t*)(sWlo + br);
            uint32_t bl1 = *(const uint32_t*)(sWlo + br + 8);
            mma16816(acc + nb*4, ah0, ah1, ah2, ah3, bh0, bh1);
            mma16816(acc + nb*4, ah0, ah1, ah2, ah3, bl0, bl1);
            mma16816(acc + nb*4, al0, al1, al2, al3, bh0, bh1);
        }
    }

    #pragma unroll
    for (int nb = 0; nb < 8; nb++) {
        const int n0 = nbase + nb * 8;
        float b0 = bias[n0 + 2*tig], b1 = bias[n0 + 2*tig + 1];
        float* r0 = dst + (m0 + g) * SB_STR;
        float* r1 = dst + (m0 + g + 8) * SB_STR;
        r0[n0 + 2*tig]     = fmaxf(acc[nb*4+0] + b0, 0.f);
        r0[n0 + 2*tig + 1] = fmaxf(acc[nb*4+1] + b1, 0.f);
        r1[n0 + 2*tig]     = fmaxf(acc[nb*4+2] + b0, 0.f);
        r1[n0 + 2*tig + 1] = fmaxf(acc[nb*4+3] + b1, 0.f);
    }
}

// ============================================================
// Fused edge pass
__global__ __launch_bounds__(256, 1)
void edge_kernel(const float* __restrict__ u,
                 const float* __restrict__ v,
                 const float* __restrict__ edge_attr,
                 const float* __restrict__ W_e1, const float* __restrict__ b_e1,
                 const float* __restrict__ W_e2, const float* __restrict__ b_e2,
                 const float* __restrict__ W_c1, const float* __restrict__ b_c1,
                 const float* __restrict__ W_cl,
                 const int*   __restrict__ edge_index)
{
    extern __shared__ __align__(16) char smem[];
    float* sPQ  = (float*)(smem + OFF_PQ);
    float* sB   = (float*)(smem + OFF_B);
    float* sIn  = (float*)(smem + OFF_IN);
    int*   sRow = (int*)  (smem + OFF_ROW);
    float* sRad = (float*)(smem + OFF_RAD);
    u64*   sWcl = (u64*)  (smem + OFF_WCL);
    __nv_bfloat16* sAhi = (__nv_bfloat16*)(smem + OFF_AHI);
    __nv_bfloat16* sAlo = (__nv_bfloat16*)(smem + OFF_ALO);
    __nv_bfloat16* sWhi = (__nv_bfloat16*)(smem + OFF_WHI);
    __nv_bfloat16* sWlo = (__nv_bfloat16*)(smem + OFF_WLO);

    const int tid = threadIdx.x;
    const int e0  = blockIdx.x * ETILE;

    // ---- setup: pack W_cl pairs, split W_e2, gather, w_diff, rad2 ----
    for (int idx = tid; idx < 64 * 22; idx += 256) {
        int kk = idx / 22, m = idx - kk * 22;
        sWcl[idx] = pk2(W_cl[(2*kk) * 22 + m], W_cl[(2*kk+1) * 22 + m]);
    }

    split_weight(W_e2, sWhi, sWlo, tid);

    {   // gather P[row]+Q[col] (4 threads per edge, float4)
        int e = tid >> 2, sub = tid & 3;
        int g = e0 + e;
        int r = edge_index[g];
        int c = edge_index[EE + g];
        const float4* Pr = (const float4*)(g_PQ + (size_t)r * 256);
        const float4* Qc = (const float4*)(g_PQ + (size_t)c * 256 + 128);
        float4* dst = (float4*)(sPQ + e * SB_STR);
        #pragma unroll
        for (int i = 0; i < 8; i++) {
            float4 a = Pr[sub + 4*i];
            float4 b = Qc[sub + 4*i];
            dst[sub + 4*i] = make_float4(a.x+b.x, a.y+b.y, a.z+b.z, a.w+b.w);
        }
        if (sub == 0) {
            sRow[e] = r;
            sIn[e * SI_STR + 33] = edge_attr[g];
            sIn[e * SI_STR + 34] = 0.f;
            sIn[e * SI_STR + 35] = 0.f;
            atomicAdd(&g_cnt[r], 1.0f);
        }
    }

    for (int idx = tid; idx < ETILE * LVV; idx += 256) {   // w_diff
        int e = idx / LVV, lv = idx - e * LVV;
        int g = e0 + e;
        int r = edge_index[g], c = edge_index[EE + g];
        float ucv = u[c * LVV + lv], vcv = v[c * LVV + lv];
        float urv = u[r * LVV + lv], vrv = v[r * LVV + lv];
        float cs = sqrtf(ucv * ucv + vcv * vcv);
        float rs = sqrtf(urv * urv + vrv * vrv);
        float rd = (ucv * urv + vcv * vrv) / (cs * rs);
        float* rrow = sIn + e * SI_STR;
        rrow[0  + lv] = rd;
        rrow[11 + lv] = cs;
        rrow[22 + lv] = rs;
    }

    for (int e = tid; e < ETILE; e += 256) {               // rad2
        int g = e0 + e;
        int c = edge_index[EE + g];
        float su = 0.f, sv = 0.f;
        #pragma unroll
        for (int lv = 0; lv < LVV; lv++) {
            float a = u[c * LVV + lv], b = v[c * LVV + lv];
            su += a * a; sv += b * b;
        }
        sRad[e * 2 + 0] = sqrtf(su);
        sRad[e * 2 + 1] = sqrtf(sv);
    }
    __syncthreads();

    const int j  = tid & 127;
    const int eg = tid >> 7;

    // ---- GEMM1 (34-k, scalar): hid = relu(PQ + w_diff@W_e1[256:289] + attr*W_e1[289] + b_e1) ----
    {
        const float* W1w = W_e1 + 256 * HH;
        float bb = b_e1[j];
        u64 acc[32];
        const float* basePQ = sPQ + (eg * 32) * SB_STR;
        #pragma unroll
        for (int e = 0; e < 32; e++) acc[e] = pk2(basePQ[e * SB_STR + j] + bb, 0.f);
        const float* base = sIn + (eg * 32) * SI_STR;
        for (int k = 0; k < 32; k += 4) {
            u64 W01 = pk2(W1w[(k+0)*HH + j], W1w[(k+1)*HH + j]);
            u64 W23 = pk2(W1w[(k+2)*HH + j], W1w[(k+3)*HH + j]);
            #pragma unroll
            for (int e = 0; e < 32; e++) {
                ulonglong2 a = *(const ulonglong2*)(base + e * SI_STR + k);
                ffma2(acc[e], a.x, W01);
                ffma2(acc[e], a.y, W23);
            }
        }
        {   // tail k=32,33
            u64 Wt = pk2(W1w[32*HH + j], W1w[33*HH + j]);
            #pragma unroll
            for (int e = 0; e < 32; e++) {
                u64 a = *(const u64*)(base + e * SI_STR + 32);
                ffma2(acc[e], a, Wt);
            }
        }
        #pragma unroll
        for (int e = 0; e < 32; e++)
            sB[(eg*32 + e)*SB_STR + j] = fmaxf(hadd2(acc[e]), 0.f);
    }
    __syncthreads();

    // ---- split hid -> bf16 hi/lo ----
    split_act(sB, SB_STR, sAhi, sAlo, tid);
    __syncthreads();

    // ---- GEMM2 (tensor): feat = relu(hid @ W_e2 + b_e2) -> sPQ ----
    mma_gemm_relu(sAhi, sAlo, sWhi, sWlo, b_e2, sPQ, tid);
    __syncthreads();

    // ---- scatter agg += feat; split feat; split W_c1 (W_e2 frags no longer read) ----
    for (int idx = tid; idx < ETILE * 32; idx += 256) {
        int e = idx >> 5, q = idx & 31;
        float4 val = *(const float4*)(sPQ + e * SB_STR + q * 4);
        float* dst = g_agg + (size_t)sRow[e] * HH + q * 4;
        asm volatile("red.global.add.v4.f32 [%0], {%1,%2,%3,%4};"
                     :: "l"(dst), "f"(val.x), "f"(val.y), "f"(val.z), "f"(val.w)
                     : "memory");
    }
    split_act(sPQ, SB_STR, sAhi, sAlo, tid);
    split_weight(W_c1, sWhi, sWlo, tid);
    __syncthreads();

    // ---- coord GEMM1 (tensor): c1 = relu(feat @ W_c1 + b_c1) -> sB ----
    mma_gemm_relu(sAhi, sAlo, sWhi, sWlo, b_c1, sB, tid);
    __syncthreads();

    // ---- coord GEMM2 (H->22, scalar) * rad2, scatter wind ----
    for (int idx = tid; idx < ETILE * 22; idx += 256) {
        int e = idx / 22, m = idx - e * 22;
        const u64* brow = (const u64*)(sB + e * SB_STR);   // 64 k-pairs
        u64 acc = 0ULL;
        #pragma unroll 8
        for (int kk = 0; kk < 64; kk++)
            ffma2(acc, brow[kk], sWcl[kk * 22 + m]);
        float r2 = sRad[e * 2 + (m >= 11 ? 1 : 0)];
        atomicAdd(&g_wind[(size_t)sRow[e] * 22 + m], hadd2(acc) * r2);
    }
}

// ============================================================
__global__ void lat_kernel() {
    int lt = blockIdx.x;          // 0..120
    int jj = threadIdx.x;         // 0..127
    float s = 0.f;
    for (int lon = 0; lon < NLON; lon++)
        s += g_agg[((size_t)lt * NLON + lon) * HH + jj];
    g_lat[lt * HH + jj] = s * (1.0f / NLON);
}

// ============================================================
// Node MLP: h_out = relu([h,agg,lat] @ W_n1 + b_n1) @ W_n2 + b_n2 + h
__global__ __launch_bounds__(256, 3)
void node_kernel(const float* __restrict__ h,
                 const float* __restrict__ W_n1, const float* __restrict__ b_n1,
                 const float* __restrict__ W_n2, const float* __restrict__ b_n2,
                 float* __restrict__ out)
{
    extern __shared__ __align__(16) float smemf[];
    float* sA = smemf;                 // [NTILE][NA_STR]
    float* sB = sA + NTILE * NA_STR;   // [NTILE][SB_STR]

    const int tid = threadIdx.x;
    const int n0  = blockIdx.x * NTILE;

    {
        int e = tid >> 3, sub = tid & 7;   // 32 rows x 8 threads
        int n = n0 + e;
        float4* dst = (float4*)(sA + e * NA_STR);
        if (n < NN) {
            const float4* hh = (const float4*)(h + (size_t)n * HH);
            const float4* aa = (const float4*)(g_agg + (size_t)n * HH);
            const float4* ll = (const float4*)(g_lat + (size_t)(n / NLON) * HH);
            #pragma unroll
            for (int i = 0; i < 4; i++) {
                dst[sub + 8*i]      = hh[sub + 8*i];
                dst[32 + sub + 8*i] = aa[sub + 8*i];
                dst[64 + sub + 8*i] = ll[sub + 8*i];
            }
        } else {
            float4 z = make_float4(0.f, 0.f, 0.f, 0.f);
            #pragma unroll
            for (int i = 0; i < 4; i++) {
                dst[sub + 8*i] = z; dst[32 + sub + 8*i] = z; dst[64 + sub + 8*i] = z;
            }
        }
    }
    __syncthreads();

    const int j  = tid & 127;
    const int eg = tid >> 7;           // 0/1, 16 rows each

    // GEMM1: [32,384]@[384,128], relu -> sB
    {
        u64 acc[16];
        #pragma unroll
        for (int e = 0; e < 16; e++) acc[e] = 0ULL;
        const float* base = sA + (eg * 16) * NA_STR;
        for (int k = 0; k < NA_STR; k += 4) {
            u64 W01 = pk2(W_n1[(k+0)*HH + j], W_n1[(k+1)*HH + j]);
            u64 W23 = pk2(W_n1[(k+2)*HH + j], W_n1[(k+3)*HH + j]);
            #pragma unroll
            for (int e = 0; e < 16; e++) {
                ulonglong2 a = *(const ulonglong2*)(base + e * NA_STR + k);
                ffma2(acc[e], a.x, W01);
                ffma2(acc[e], a.y, W23);
            }
        }
        float bb = b_n1[j];
        #pragma unroll
        for (int e = 0; e < 16; e++)
            sB[(eg*16 + e)*SB_STR + j] = fmaxf(hadd2(acc[e]) + bb, 0.f);
    }
    __syncthreads();

    // GEMM2: [32,128]@[128,128] + b + residual -> out
    {
        u64 acc[16];
        #pragma unroll
        for (int e = 0; e < 16; e++) acc[e] = 0ULL;
        const float* base = sB + (eg * 16) * SB_STR;
        for (int k = 0; k < 128; k += 4) {
            u64 W01 = pk2(W_n2[(k+0)*HH + j], W_n2[(k+1)*HH + j]);
            u64 W23 = pk2(W_n2[(k+2)*HH + j], W_n2[(k+3)*HH + j]);
            #pragma unroll
            for (int e = 0; e < 16; e++) {
                ulonglong2 a = *(const ulonglong2*)(base + e * SB_STR + k);
                ffma2(acc[e], a.x, W01);
                ffma2(acc[e], a.y, W23);
            }
        }
        float bb = b_n2[j];
        #pragma unroll
        for (int e = 0; e < 16; e++) {
            int n = n0 + eg*16 + e;
            if (n < NN)
                out[(size_t)n * HH + j] = hadd2(acc[e]) + bb + h[(size_t)n * HH + j];
        }
    }
}

// ============================================================
__global__ void coord_kernel(float* __restrict__ out) {
    int i = blockIdx.x * 256 + threadIdx.x;     // over NN*22
    if (i >= NN * 22) return;
    int n = i / 22, m = i - n * 22;
    float cnt = fmaxf(g_cnt[n], 1.0f);
    float val = g_wind[i] / cnt;
    val = fminf(fmaxf(val, -100.0f), 100.0f);
    int lv = (m >= 11) ? (m - 11) : m;
    float* o = out + (size_t)NN * HH + (m >= 11 ? NN * LVV : 0) + n * LVV + lv;
    *o = val;
}

// ============================================================
extern "C" void kernel_launch(void* const* d_in, const int* in_sizes, int n_in,
                              void* d_out, int out_size)
{
    const float* h         = (const float*)d_in[0];
    const float* u         = (const float*)d_in[1];
    const float* v         = (const float*)d_in[2];
    const float* edge_attr = (const float*)d_in[3];
    const float* W_e1      = (const float*)d_in[4];
    const float* b_e1      = (const float*)d_in[5];
    const float* W_e2      = (const float*)d_in[6];
    const float* b_e2      = (const float*)d_in[7];
    const float* W_n1      = (const float*)d_in[8];
    const float* b_n1      = (const float*)d_in[9];
    const float* W_n2      = (const float*)d_in[10];
    const float* b_n2      = (const float*)d_in[11];
    const float* W_c1      = (const float*)d_in[12];
    const float* b_c1      = (const float*)d_in[13];
    const float* W_cl      = (const float*)d_in[14];
    const int*   edge_index= (const int*)  d_in[15];
    float* out = (float*)d_out;

    const int PQ_SMEM   = 64 * SB_STR * 4;
    const int NODE_SMEM = (NTILE * NA_STR + NTILE * SB_STR) * 4;
    cudaFuncSetAttribute(pq_kernel,   cudaFuncAttributeMaxDynamicSharedMemorySize, PQ_SMEM);
    cudaFuncSetAttribute(edge_kernel, cudaFuncAttributeMaxDynamicSharedMemorySize, EDGE_SMEM);
    cudaFuncSetAttribute(node_kernel, cudaFuncAttributeMaxDynamicSharedMemorySize, NODE_SMEM);

    zero_kernel<<<(NN * HH + 255) / 256, 256>>>();

    pq_kernel<<<(NN + 63) / 64, 256, PQ_SMEM>>>(h, W_e1);

    edge_kernel<<<EE / ETILE, 256, EDGE_SMEM>>>(u, v, edge_attr,
                                                W_e1, b_e1, W_e2, b_e2,
                                                W_c1, b_c1, W_cl, edge_index);

    lat_kernel<<<NLAT, HH>>>();

    node_kernel<<<(NN + NTILE - 1) / NTILE, 256, NODE_SMEM>>>(h, W_n1, b_n1, W_n2, b_n2, out);

    coord_kernel<<<(NN * 22 + 255) / 256, 256>>>(out);
}

// round 7
// speedup vs baseline: 1.9816x; 1.2150x over previous
#include <cuda_runtime.h>
#include <cuda_bf16.h>
#include <cstdint>

// Problem constants
#define NN      29040        // nodes (121*240)
#define EE      464640       // edges (NN*16)
#define HH      128          // hidden
#define LVV     11           // levels
#define NLAT    121
#define NLON    240

// Edge kernel tiling
#define ETILE   64
#define SI_STR  36           // w_diff(33)+attr(1), padded
#define SB_STR  132          // padded 128 (fp32 buffers)
#define AK      136          // bf16 activation row stride (128 + 8 pad)
#define WK      136          // bf16 weight row stride

// Node kernel tiling
#define NTILE   32
#define NA_STR  384          // 3*H

typedef unsigned long long u64;

// ---- packed f32x2 helpers ----
__device__ __forceinline__ u64 pk2(float lo, float hi) {
    u64 r; asm("mov.b64 %0, {%1,%2};" : "=l"(r) : "f"(lo), "f"(hi)); return r;
}
__device__ __forceinline__ void ffma2(u64& acc, u64 a, u64 b) {
    asm("fma.rn.f32x2 %0, %1, %2, %0;" : "+l"(acc) : "l"(a), "l"(b));
}
__device__ __forceinline__ float hadd2(u64 x) {
    float lo, hi; asm("mov.b64 {%0,%1}, %2;" : "=f"(lo), "=f"(hi) : "l"(x));
    return lo + hi;
}

// ---- bf16 split helpers ----
__device__ __forceinline__ void bf16split(float x, __nv_bfloat16& hi, __nv_bfloat16& lo) {
    hi = __float2bfloat16_rn(x);
    lo = __float2bfloat16_rn(x - __bfloat162float(hi));
}

// ---- m16n8k16 bf16 MMA ----
__device__ __forceinline__ void mma16816(float* c,
    uint32_t a0, uint32_t a1, uint32_t a2, uint32_t a3,
    uint32_t b0, uint32_t b1)
{
    asm volatile(
        "mma.sync.aligned.m16n8k16.row.col.f32.bf16.bf16.f32 "
        "{%0,%1,%2,%3}, {%4,%5,%6,%7}, {%8,%9}, {%0,%1,%2,%3};"
        : "+f"(c[0]), "+f"(c[1]), "+f"(c[2]), "+f"(c[3])
        : "r"(a0), "r"(a1), "r"(a2), "r"(a3), "r"(b0), "r"(b1));
}

// ---- scratch (no allocation allowed) ----
__device__ float g_agg[NN * HH];
__device__ float g_wind[NN * 22];
__device__ float g_cnt[NN];
__device__ float g_lat[NLAT * HH];
__device__ float g_PQ[NN * 256];
// Pre-split weights, already in MMA [n][k] layout with WK padding:
__device__ __align__(16) __nv_bfloat16 g_We2hi[HH * WK];
__device__ __align__(16) __nv_bfloat16 g_We2lo[HH * WK];
__device__ __align__(16) __nv_bfloat16 g_Wc1hi[HH * WK];
__device__ __align__(16) __nv_bfloat16 g_Wc1lo[HH * WK];

// ---- edge-kernel SMEM layout (byte offsets) ----
#define OFF_F    0                                   // [64][132] f32  PQ / c1
#define OFF_IN   (OFF_F   + ETILE*SB_STR*4)          // [64][36]  f32
#define OFF_ROW  (OFF_IN  + ETILE*SI_STR*4)          // [64] int
#define OFF_RAD  (OFF_ROW + ETILE*4)                 // [64][2] f32
#define OFF_WCL  (OFF_RAD + ETILE*2*4)               // [64][22] u64
#define OFF_AHI  (OFF_WCL + 64*22*8)                 // [64][AK] bf16 (hid/feat hi)
#define OFF_ALO  (OFF_AHI + ETILE*AK*2)
#define OFF_WHI  (OFF_ALO + ETILE*AK*2)              // [128][WK] bf16
#define OFF_WLO  (OFF_WHI + HH*WK*2)
#define EDGE_SMEM (OFF_WLO + HH*WK*2)                // 159488 bytes

// ============================================================
__global__ void zero_kernel() {
    int i = blockIdx.x * 256 + threadIdx.x;
    if (i < NN * HH) g_agg[i] = 0.f;
    if (i < NN * 22) g_wind[i] = 0.f;
    if (i < NN)      g_cnt[i] = 0.f;
}

// ============================================================
// One-time weight split: W[k][n] fp32 -> hi/lo bf16 at [n*WK + k]
__global__ void wsplit_kernel(const float* __restrict__ We2,
                              const float* __restrict__ Wc1)
{
    int idx = blockIdx.x * 256 + threadIdx.x;     // over 2*16384
    if (idx >= 2 * HH * HH) return;
    int w = idx >> 14, r = idx & (HH * HH - 1);
    int k = r >> 7, n = r & 127;
    float x = (w ? Wc1 : We2)[k * HH + n];
    __nv_bfloat16 hi, lo; bf16split(x, hi, lo);
    if (w) { g_Wc1hi[n * WK + k] = hi; g_Wc1lo[n * WK + k] = lo; }
    else   { g_We2hi[n * WK + k] = hi; g_We2lo[n * WK + k] = lo; }
}

// ============================================================
// Precompute P = h @ W_e1[0:128,:], Q = h @ W_e1[128:256,:]
__global__ __launch_bounds__(256, 2)
void pq_kernel(const float* __restrict__ h,
               const float* __restrict__ W_e1)
{
    extern __shared__ __align__(16) float smemf[];
    float* sH = smemf;                 // [64][SB_STR]

    const int tid = threadIdx.x;
    const int n0  = blockIdx.x * 64;

    {
        int e = tid >> 2, sub = tid & 3;
        int n = n0 + e;
        float4* dst = (float4*)(sH + e * SB_STR);
        if (n < NN) {
            const float4* hh = (const float4*)(h + (size_t)n * HH);
            #pragma unroll
            for (int i = 0; i < 8; i++) dst[sub + 4*i] = hh[sub + 4*i];
        } else {
            float4 z = make_float4(0.f,0.f,0.f,0.f);
            #pragma unroll
            for (int i = 0; i < 8; i++) dst[sub + 4*i] = z;
        }
    }
    __syncthreads();

    const int j  = tid & 127;
    const int eg = tid >> 7;

    #pragma unroll
    for (int half = 0; half < 2; half++) {
        const float* W = W_e1 + half * 128 * HH;
        u64 acc[32];
        #pragma unroll
        for (int e = 0; e < 32; e++) acc[e] = 0ULL;
        const float* base = sH + (eg * 32) * SB_STR;
        for (int k = 0; k < 128; k += 4) {
            u64 W01 = pk2(W[(k+0)*HH + j], W[(k+1)*HH + j]);
            u64 W23 = pk2(W[(k+2)*HH + j], W[(k+3)*HH + j]);
            #pragma unroll
            for (int e = 0; e < 32; e++) {
                ulonglong2 a = *(const ulonglong2*)(base + e * SB_STR + k);
                ffma2(acc[e], a.x, W01);
                ffma2(acc[e], a.y, W23);
            }
        }
        #pragma unroll
        for (int e = 0; e < 32; e++) {
            int n = n0 + eg*32 + e;
            if (n < NN) g_PQ[(size_t)n * 256 + half * 128 + j] = hadd2(acc[e]);
        }
    }
}

// ============================================================
// Vectorized copy of pre-split weights into SMEM
__device__ __forceinline__ void copy_weights(const __nv_bfloat16* __restrict__ ghi,
                                             const __nv_bfloat16* __restrict__ glo,
                                             __nv_bfloat16* sWhi, __nv_bfloat16* sWlo,
                                             int tid)
{
    const uint4* srcH = (const uint4*)ghi;
    const uint4* srcL = (const uint4*)glo;
    uint4* dstH = (uint4*)sWhi;
    uint4* dstL = (uint4*)sWlo;
    const int nvec = HH * WK * 2 / 16;    // 2176
    for (int i = tid; i < nvec; i += 256) {
        dstH[i] = srcH[i];
        dstL[i] = srcL[i];
    }
}

// MMA compute only (no epilogue). acc layout: [nb*4 + {r0c0,r0c1,r1c0,r1c1}]
__device__ __forceinline__ void mma_compute(float (&acc)[32],
    const __nv_bfloat16* __restrict__ sAhi, const __nv_bfloat16* __restrict__ sAlo,
    const __nv_bfloat16* __restrict__ sWhi, const __nv_bfloat16* __restrict__ sWlo,
    int tid)
{
    const int w = tid >> 5, lane = tid & 31;
    const int g = lane >> 2, tig = lane & 3;
    const int m0 = (w & 3) * 16;
    const int nbase = (w >> 2) * 64;

    #pragma unroll
    for (int i = 0; i < 32; i++) acc[i] = 0.f;

    #pragma unroll
    for (int kb = 0; kb < 8; kb++) {
        const int k0 = kb * 16;
        const int ar = (m0 + g) * AK + k0 + 2 * tig;
        uint32_t ah0 = *(const uint32_t*)(sAhi + ar);
        uint32_t ah1 = *(const uint32_t*)(sAhi + ar + 8 * AK);
        uint32_t ah2 = *(const uint32_t*)(sAhi + ar + 8);
        uint32_t ah3 = *(const uint32_t*)(sAhi + ar + 8 * AK + 8);
        uint32_t al0 = *(const uint32_t*)(sAlo + ar);
        uint32_t al1 = *(const uint32_t*)(sAlo + ar + 8 * AK);
        uint32_t al2 = *(const uint32_t*)(sAlo + ar + 8);
        uint32_t al3 = *(const uint32_t*)(sAlo + ar + 8 * AK + 8);
        #pragma unroll
        for (int nb = 0; nb < 8; nb++) {
            const int n0 = nbase + nb * 8;
            const int br = (n0 + g) * WK + k0 + 2 * tig;
            uint32_t bh0 = *(const uint32_t*)(sWhi + br);
            uint32_t bh1 = *(const uint32_t*)(sWhi + br + 8);
            uint32_t bl0 = *(const uint32_t*)(sWlo + br);
            uint32_t bl1 = *(const uint32_t*)(sWlo + br + 8);
            mma16816(acc + nb*4, ah0, ah1, ah2, ah3, bh0, bh1);
            mma16816(acc + nb*4, ah0, ah1, ah2, ah3, bl0, bl1);
            mma16816(acc + nb*4, al0, al1, al2, al3, bh0, bh1);
        }
    }
}

// ============================================================
// Fused edge pass
__global__ __launch_bounds__(256, 1)
void edge_kernel(const float* __restrict__ u,
                 const float* __restrict__ v,
                 const float* __restrict__ edge_attr,
                 const float* __restrict__ W_e1, const float* __restrict__ b_e1,
                 const float* __restrict__ b_e2,
                 const float* __restrict__ b_c1,
                 const float* __restrict__ W_cl,
                 const int*   __restrict__ edge_index)
{
    extern __shared__ __align__(16) char smem[];
    float* sF   = (float*)(smem + OFF_F);
    float* sIn  = (float*)(smem + OFF_IN);
    int*   sRow = (int*)  (smem + OFF_ROW);
    float* sRad = (float*)(smem + OFF_RAD);
    u64*   sWcl = (u64*)  (smem + OFF_WCL);
    __nv_bfloat16* sAhi = (__nv_bfloat16*)(smem + OFF_AHI);
    __nv_bfloat16* sAlo = (__nv_bfloat16*)(smem + OFF_ALO);
    __nv_bfloat16* sWhi = (__nv_bfloat16*)(smem + OFF_WHI);
    __nv_bfloat16* sWlo = (__nv_bfloat16*)(smem + OFF_WLO);

    const int tid = threadIdx.x;
    const int e0  = blockIdx.x * ETILE;

    // ---- setup ----
    copy_weights(g_We2hi, g_We2lo, sWhi, sWlo, tid);

    for (int idx = tid; idx < 64 * 22; idx += 256) {
        int kk = idx / 22, m = idx - kk * 22;
        sWcl[idx] = pk2(W_cl[(2*kk) * 22 + m], W_cl[(2*kk+1) * 22 + m]);
    }

    {   // gather P[row]+Q[col]
        int e = tid >> 2, sub = tid & 3;
        int g = e0 + e;
        int r = edge_index[g];
        int c = edge_index[EE + g];
        const float4* Pr = (const float4*)(g_PQ + (size_t)r * 256);
        const float4* Qc = (const float4*)(g_PQ + (size_t)c * 256 + 128);
        float4* dst = (float4*)(sF + e * SB_STR);
        #pragma unroll
        for (int i = 0; i < 8; i++) {
            float4 a = Pr[sub + 4*i];
            float4 b = Qc[sub + 4*i];
            dst[sub + 4*i] = make_float4(a.x+b.x, a.y+b.y, a.z+b.z, a.w+b.w);
        }
        if (sub == 0) {
            sRow[e] = r;
            sIn[e * SI_STR + 33] = edge_attr[g];
            sIn[e * SI_STR + 34] = 0.f;
            sIn[e * SI_STR + 35] = 0.f;
            atomicAdd(&g_cnt[r], 1.0f);
        }
    }

    for (int idx = tid; idx < ETILE * LVV; idx += 256) {   // w_diff
        int e = idx / LVV, lv = idx - e * LVV;
        int g = e0 + e;
        int r = edge_index[g], c = edge_index[EE + g];
        float ucv = u[c * LVV + lv], vcv = v[c * LVV + lv];
        float urv = u[r * LVV + lv], vrv = v[r * LVV + lv];
        float cs = sqrtf(ucv * ucv + vcv * vcv);
        float rs = sqrtf(urv * urv + vrv * vrv);
        float rd = (ucv * urv + vcv * vrv) / (cs * rs);
        float* rrow = sIn + e * SI_STR;
        rrow[0  + lv] = rd;
        rrow[11 + lv] = cs;
        rrow[22 + lv] = rs;
    }

    for (int e = tid; e < ETILE; e += 256) {               // rad2
        int g = e0 + e;
        int c = edge_index[EE + g];
        float su = 0.f, sv = 0.f;
        #pragma unroll
        for (int lv = 0; lv < LVV; lv++) {
            float a = u[c * LVV + lv], b = v[c * LVV + lv];
            su += a * a; sv += b * b;
        }
        sRad[e * 2 + 0] = sqrtf(su);
        sRad[e * 2 + 1] = sqrtf(sv);
    }
    __syncthreads();

    const int j  = tid & 127;
    const int eg = tid >> 7;

    // ---- GEMM1 (34-k, scalar): hid = relu(PQ + w_diff@W_e1[256:] + b_e1)
    //      epilogue writes bf16 hi/lo splits directly ----
    {
        const float* W1w = W_e1 + 256 * HH;
        float bb = b_e1[j];
        u64 acc[32];
        const float* basePQ = sF + (eg * 32) * SB_STR;
        #pragma unroll
        for (int e = 0; e < 32; e++) acc[e] = pk2(basePQ[e * SB_STR + j] + bb, 0.f);
        const float* base = sIn + (eg * 32) * SI_STR;
        for (int k = 0; k < 32; k += 4) {
            u64 W01 = pk2(W1w[(k+0)*HH + j], W1w[(k+1)*HH + j]);
            u64 W23 = pk2(W1w[(k+2)*HH + j], W1w[(k+3)*HH + j]);
            #pragma unroll
            for (int e = 0; e < 32; e++) {
                ulonglong2 a = *(const ulonglong2*)(base + e * SI_STR + k);
                ffma2(acc[e], a.x, W01);
                ffma2(acc[e], a.y, W23);
            }
        }
        {
            u64 Wt = pk2(W1w[32*HH + j], W1w[33*HH + j]);
            #pragma unroll
            for (int e = 0; e < 32; e++) {
                u64 a = *(const u64*)(base + e * SI_STR + 32);
                ffma2(acc[e], a, Wt);
            }
        }
        #pragma unroll
        for (int e = 0; e < 32; e++) {
            float hv = fmaxf(hadd2(acc[e]), 0.f);
            __nv_bfloat16 hi, lo; bf16split(hv, hi, lo);
            int row = eg*32 + e;
            sAhi[row * AK + j] = hi;
            sAlo[row * AK + j] = lo;
        }
    }
    __syncthreads();

    // ---- GEMM2 (tensor): feat = relu(hid @ W_e2 + b_e2)
    //      epilogue: scatter to g_agg + write bf16 splits in place ----
    {
        float acc[32];
        mma_compute(acc, sAhi, sAlo, sWhi, sWlo, tid);
        __syncthreads();   // all reads of sA (hid) and sW (We2) complete

        const int w = tid >> 5, lane = tid & 31;
        const int g = lane >> 2, tig = lane & 3;
        const int m0 = (w & 3) * 16;
        const int nbase = (w >> 2) * 64;
        const int r0 = sRow[m0 + g], r1 = sRow[m0 + g + 8];
        #pragma unroll
        for (int nb = 0; nb < 8; nb++) {
            const int n0 = nbase + nb * 8 + 2 * tig;
            float b0 = b_e2[n0], b1 = b_e2[n0 + 1];
            float v00 = fmaxf(acc[nb*4+0] + b0, 0.f);
            float v01 = fmaxf(acc[nb*4+1] + b1, 0.f);
            float v10 = fmaxf(acc[nb*4+2] + b0, 0.f);
            float v11 = fmaxf(acc[nb*4+3] + b1, 0.f);
            asm volatile("red.global.add.v2.f32 [%0], {%1,%2};"
                         :: "l"(g_agg + (size_t)r0 * HH + n0), "f"(v00), "f"(v01) : "memory");
            asm volatile("red.global.add.v2.f32 [%0], {%1,%2};"
                         :: "l"(g_agg + (size_t)r1 * HH + n0), "f"(v10), "f"(v11) : "memory");
            __nv_bfloat16 h0,l0,h1,l1;
            bf16split(v00, h0, l0); bf16split(v01, h1, l1);
            __nv_bfloat162 th; th.x = h0; th.y = h1;
            __nv_bfloat162 tl; tl.x = l0; tl.y = l1;
            *(__nv_bfloat162*)(sAhi + (m0 + g) * AK + n0) = th;
            *(__nv_bfloat162*)(sAlo + (m0 + g) * AK + n0) = tl;
            bf16split(v10, h0, l0); bf16split(v11, h1, l1);
            th.x = h0; th.y = h1; tl.x = l0; tl.y = l1;
            *(__nv_bfloat162*)(sAhi + (m0 + g + 8) * AK + n0) = th;
            *(__nv_bfloat162*)(sAlo + (m0 + g + 8) * AK + n0) = tl;
        }
    }

    // ---- swap weights to W_c1 (sW reads finished before the sync above) ----
    copy_weights(g_Wc1hi, g_Wc1lo, sWhi, sWlo, tid);
    __syncthreads();

    // ---- coord GEMM1 (tensor): c1 = relu(feat @ W_c1 + b_c1) -> sF (f32) ----
    {
        float acc[32];
        mma_compute(acc, sAhi, sAlo, sWhi, sWlo, tid);

        const int w = tid >> 5, lane = tid & 31;
        const int g = lane >> 2, tig = lane & 3;
        const int m0 = (w & 3) * 16;
        const int nbase = (w >> 2) * 64;
        float* rowp0 = sF + (m0 + g) * SB_STR;
        float* rowp1 = sF + (m0 + g + 8) * SB_STR;
        #pragma unroll
        for (int nb = 0; nb < 8; nb++) {
            const int n0 = nbase + nb * 8 + 2 * tig;
            float b0 = b_c1[n0], b1 = b_c1[n0 + 1];
            rowp0[n0]     = fmaxf(acc[nb*4+0] + b0, 0.f);
            rowp0[n0 + 1] = fmaxf(acc[nb*4+1] + b1, 0.f);
            rowp1[n0]     = fmaxf(acc[nb*4+2] + b0, 0.f);
            rowp1[n0 + 1] = fmaxf(acc[nb*4+3] + b1, 0.f);
        }
    }
    __syncthreads();

    // ---- coord GEMM2 (H->22, scalar) * rad2, scatter wind ----
    for (int idx = tid; idx < ETILE * 22; idx += 256) {
        int e = idx / 22, m = idx - e * 22;
        const u64* brow = (const u64*)(sF + e * SB_STR);
        u64 acc = 0ULL;
        #pragma unroll 8
        for (int kk = 0; kk < 64; kk++)
            ffma2(acc, brow[kk], sWcl[kk * 22 + m]);
        float r2 = sRad[e * 2 + (m >= 11 ? 1 : 0)];
        atomicAdd(&g_wind[(size_t)sRow[e] * 22 + m], hadd2(acc) * r2);
    }
}

// ============================================================
__global__ void lat_kernel() {
    int lt = blockIdx.x;
    int jj = threadIdx.x;
    float s = 0.f;
    for (int lon = 0; lon < NLON; lon++)
        s += g_agg[((size_t)lt * NLON + lon) * HH + jj];
    g_lat[lt * HH + jj] = s * (1.0f / NLON);
}

// ============================================================
__global__ __launch_bounds__(256, 3)
void node_kernel(const float* __restrict__ h,
                 const float* __restrict__ W_n1, const float* __restrict__ b_n1,
                 const float* __restrict__ W_n2, const float* __restrict__ b_n2,
                 float* __restrict__ out)
{
    extern __shared__ __align__(16) float smemf[];
    float* sA = smemf;
    float* sB = sA + NTILE * NA_STR;

    const int tid = threadIdx.x;
    const int n0  = blockIdx.x * NTILE;

    {
        int e = tid >> 3, sub = tid & 7;
        int n = n0 + e;
        float4* dst = (float4*)(sA + e * NA_STR);
        if (n < NN) {
            const float4* hh = (const float4*)(h + (size_t)n * HH);
            const float4* aa = (const float4*)(g_agg + (size_t)n * HH);
            const float4* ll = (const float4*)(g_lat + (size_t)(n / NLON) * HH);
            #pragma unroll
            for (int i = 0; i < 4; i++) {
                dst[sub + 8*i]      = hh[sub + 8*i];
                dst[32 + sub + 8*i] = aa[sub + 8*i];
                dst[64 + sub + 8*i] = ll[sub + 8*i];
            }
        } else {
            float4 z = make_float4(0.f, 0.f, 0.f, 0.f);
            #pragma unroll
            for (int i = 0; i < 4; i++) {
                dst[sub + 8*i] = z; dst[32 + sub + 8*i] = z; dst[64 + sub + 8*i] = z;
            }
        }
    }
    __syncthreads();

    const int j  = tid & 127;
    const int eg = tid >> 7;

    {
        u64 acc[16];
        #pragma unroll
        for (int e = 0; e < 16; e++) acc[e] = 0ULL;
        const float* base = sA + (eg * 16) * NA_STR;
        for (int k = 0; k < NA_STR; k += 4) {
            u64 W01 = pk2(W_n1[(k+0)*HH + j], W_n1[(k+1)*HH + j]);
            u64 W23 = pk2(W_n1[(k+2)*HH + j], W_n1[(k+3)*HH + j]);
            #pragma unroll
            for (int e = 0; e < 16; e++) {
                ulonglong2 a = *(const ulonglong2*)(base + e * NA_STR + k);
                ffma2(acc[e], a.x, W01);
                ffma2(acc[e], a.y, W23);
            }
        }
        float bb = b_n1[j];
        #pragma unroll
        for (int e = 0; e < 16; e++)
            sB[(eg*16 + e)*SB_STR + j] = fmaxf(hadd2(acc[e]) + bb, 0.f);
    }
    __syncthreads();

    {
        u64 acc[16];
        #pragma unroll
        for (int e = 0; e < 16; e++) acc[e] = 0ULL;
        const float* base = sB + (eg * 16) * SB_STR;
        for (int k = 0; k < 128; k += 4) {
            u64 W01 = pk2(W_n2[(k+0)*HH + j], W_n2[(k+1)*HH + j]);
            u64 W23 = pk2(W_n2[(k+2)*HH + j], W_n2[(k+3)*HH + j]);
            #pragma unroll
            for (int e = 0; e < 16; e++) {
                ulonglong2 a = *(const ulonglong2*)(base + e * SB_STR + k);
                ffma2(acc[e], a.x, W01);
                ffma2(acc[e], a.y, W23);
            }
        }
        float bb = b_n2[j];
        #pragma unroll
        for (int e = 0; e < 16; e++) {
            int n = n0 + eg*16 + e;
            if (n < NN)
                out[(size_t)n * HH + j] = hadd2(acc[e]) + bb + h[(size_t)n * HH + j];
        }
    }
}

// ============================================================
__global__ void coord_kernel(float* __restrict__ out) {
    int i = blockIdx.x * 256 + threadIdx.x;
    if (i >= NN * 22) return;
    int n = i / 22, m = i - n * 22;
    float cnt = fmaxf(g_cnt[n], 1.0f);
    float val = g_wind[i] / cnt;
    val = fminf(fmaxf(val, -100.0f), 100.0f);
    int lv = (m >= 11) ? (m - 11) : m;
    float* o = out + (size_t)NN * HH + (m >= 11 ? NN * LVV : 0) + n * LVV + lv;
    *o = val;
}

// ============================================================
extern "C" void kernel_launch(void* const* d_in, const int* in_sizes, int n_in,
                              void* d_out, int out_size)
{
    const float* h         = (const float*)d_in[0];
    const float* u         = (const float*)d_in[1];
    const float* v         = (const float*)d_in[2];
    const float* edge_attr = (const float*)d_in[3];
    const float* W_e1      = (const float*)d_in[4];
    const float* b_e1      = (const float*)d_in[5];
    const float* W_e2      = (const float*)d_in[6];
    const float* b_e2      = (const float*)d_in[7];
    const float* W_n1      = (const float*)d_in[8];
    const float* b_n1      = (const float*)d_in[9];
    const float* W_n2      = (const float*)d_in[10];
    const float* b_n2      = (const float*)d_in[11];
    const float* W_c1      = (const float*)d_in[12];
    const float* b_c1      = (const float*)d_in[13];
    const float* W_cl      = (const float*)d_in[14];
    const int*   edge_index= (const int*)  d_in[15];
    float* out = (float*)d_out;

    const int PQ_SMEM   = 64 * SB_STR * 4;
    const int NODE_SMEM = (NTILE * NA_STR + NTILE * SB_STR) * 4;
    cudaFuncSetAttribute(pq_kernel,   cudaFuncAttributeMaxDynamicSharedMemorySize, PQ_SMEM);
    cudaFuncSetAttribute(edge_kernel, cudaFuncAttributeMaxDynamicSharedMemorySize, EDGE_SMEM);
    cudaFuncSetAttribute(node_kernel, cudaFuncAttributeMaxDynamicSharedMemorySize, NODE_SMEM);

    zero_kernel<<<(NN * HH + 255) / 256, 256>>>();
    wsplit_kernel<<<(2 * HH * HH + 255) / 256, 256>>>(W_e2, W_c1);

    pq_kernel<<<(NN + 63) / 64, 256, PQ_SMEM>>>(h, W_e1);

    edge_kernel<<<EE / ETILE, 256, EDGE_SMEM>>>(u, v, edge_attr,
                                                W_e1, b_e1, b_e2,
                                                b_c1, W_cl, edge_index);

    lat_kernel<<<NLAT, HH>>>();

    node_kernel<<<(NN + NTILE - 1) / NTILE, 256, NODE_SMEM>>>(h, W_n1, b_n1, W_n2, b_n2, out);

    coord_kernel<<<(NN * 22 + 255) / 256, 256>>>(out);
}

// round 9
// speedup vs baseline: 2.3379x; 1.1798x over previous
#include <cuda_runtime.h>
#include <cuda_bf16.h>
#include <cstdint>

// Problem constants
#define NN      29040        // nodes (121*240)
#define EE      464640       // edges (NN*16)
#define HH      128          // hidden
#define LVV     11           // levels
#define NLAT    121
#define NLON    240

// Edge kernel tiling
#define ETILE   128
#define ETHREADS 512
#define SI_STR  36           // w_diff(33)+attr(1), padded
#define SB_STR  132          // padded 128 (fp32 buffers, node/pq kernels)
#define AK      136          // bf16 activation row stride (conflict-free)
#define WK      136          // bf16 weight row stride

// Node kernel tiling
#define NTILE   32
#define NA_STR  384          // 3*H

typedef unsigned long long u64;

// ---- packed f32x2 helpers ----
__device__ __forceinline__ u64 pk2(float lo, float hi) {
    u64 r; asm("mov.b64 %0, {%1,%2};" : "=l"(r) : "f"(lo), "f"(hi)); return r;
}
__device__ __forceinline__ void ffma2(u64& acc, u64 a, u64 b) {
    asm("fma.rn.f32x2 %0, %1, %2, %0;" : "+l"(acc) : "l"(a), "l"(b));
}
__device__ __forceinline__ float hadd2(u64 x) {
    float lo, hi; asm("mov.b64 {%0,%1}, %2;" : "=f"(lo), "=f"(hi) : "l"(x));
    return lo + hi;
}

// ---- bf16 split helpers ----
__device__ __forceinline__ void bf16split(float x, __nv_bfloat16& hi, __nv_bfloat16& lo) {
    hi = __float2bfloat16_rn(x);
    lo = __float2bfloat16_rn(x - __bfloat162float(hi));
}

// ---- m16n8k16 bf16 MMA ----
__device__ __forceinline__ void mma16816(float* c,
    uint32_t a0, uint32_t a1, uint32_t a2, uint32_t a3,
    uint32_t b0, uint32_t b1)
{
    asm volatile(
        "mma.sync.aligned.m16n8k16.row.col.f32.bf16.bf16.f32 "
        "{%0,%1,%2,%3}, {%4,%5,%6,%7}, {%8,%9}, {%0,%1,%2,%3};"
        : "+f"(c[0]), "+f"(c[1]), "+f"(c[2]), "+f"(c[3])
        : "r"(a0), "r"(a1), "r"(a2), "r"(a3), "r"(b0), "r"(b1));
}

// ---- scratch ----
__device__ float g_agg[NN * HH];
__device__ float g_wind[NN * 22];
__device__ float g_cnt[NN];
__device__ float g_lat[NLAT * HH];
__device__ float g_PQ[NN * 256];
__device__ __align__(16) __nv_bfloat16 g_We2hi[HH * WK];
__device__ __align__(16) __nv_bfloat16 g_We2lo[HH * WK];
__device__ __align__(16) __nv_bfloat16 g_Wc1hi[HH * WK];
__device__ __align__(16) __nv_bfloat16 g_Wc1lo[HH * WK];

// ---- edge-kernel SMEM layout (byte offsets) ----
// sIn (GEMM1 inputs) and sWcl (coordGEMM2 weights) are UNIONed: sIn dead after GEMM1.
#define OFF_UNION 0
#define SZ_UNION  (ETILE*SI_STR*4)            // 18432 >= 64*22*8
#define OFF_ROW   (OFF_UNION + SZ_UNION)      // 18432
#define OFF_RAD   (OFF_ROW + ETILE*4)         // 18944
#define OFF_AHI   (OFF_RAD + ETILE*2*4)       // 19968
#define OFF_ALO   (OFF_AHI + ETILE*AK*2)      // 54784
#define OFF_WHI   (OFF_ALO + ETILE*AK*2)      // 89600
#define OFF_WLO   (OFF_WHI + HH*WK*2)         // 124416
#define EDGE_SMEM (OFF_WLO + HH*WK*2)         // 159232 bytes

// ============================================================
__global__ void zero_kernel() {
    int i = blockIdx.x * 256 + threadIdx.x;
    if (i < NN * HH) g_agg[i] = 0.f;
    if (i < NN * 22) g_wind[i] = 0.f;
    if (i < NN)      g_cnt[i] = 0.f;
}

// ============================================================
// One-time weight split: W[k][n] fp32 -> hi/lo bf16 at [n*WK + k]
__global__ void wsplit_kernel(const float* __restrict__ We2,
                              const float* __restrict__ Wc1)
{
    int idx = blockIdx.x * 256 + threadIdx.x;
    if (idx >= 2 * HH * HH) return;
    int w = idx >> 14, r = idx & (HH * HH - 1);
    int k = r >> 7, n = r & 127;
    float x = (w ? Wc1 : We2)[k * HH + n];
    __nv_bfloat16 hi, lo; bf16split(x, hi, lo);
    if (w) { g_Wc1hi[n * WK + k] = hi; g_Wc1lo[n * WK + k] = lo; }
    else   { g_We2hi[n * WK + k] = hi; g_We2lo[n * WK + k] = lo; }
}

// ============================================================
// Precompute P = h @ W_e1[0:128,:], Q = h @ W_e1[128:256,:]
__global__ __launch_bounds__(256, 2)
void pq_kernel(const float* __restrict__ h,
               const float* __restrict__ W_e1)
{
    extern __shared__ __align__(16) float smemf[];
    float* sH = smemf;                 // [64][SB_STR]

    const int tid = threadIdx.x;
    const int n0  = blockIdx.x * 64;

    {
        int e = tid >> 2, sub = tid & 3;
        int n = n0 + e;
        float4* dst = (float4*)(sH + e * SB_STR);
        if (n < NN) {
            const float4* hh = (const float4*)(h + (size_t)n * HH);
            #pragma unroll
            for (int i = 0; i < 8; i++) dst[sub + 4*i] = hh[sub + 4*i];
        } else {
            float4 z = make_float4(0.f,0.f,0.f,0.f);
            #pragma unroll
            for (int i = 0; i < 8; i++) dst[sub + 4*i] = z;
        }
    }
    __syncthreads();

    const int j  = tid & 127;
    const int eg = tid >> 7;

    #pragma unroll
    for (int half = 0; half < 2; half++) {
        const float* W = W_e1 + half * 128 * HH;
        u64 acc[32];
        #pragma unroll
        for (int e = 0; e < 32; e++) acc[e] = 0ULL;
        const float* base = sH + (eg * 32) * SB_STR;
        for (int k = 0; k < 128; k += 4) {
            u64 W01 = pk2(W[(k+0)*HH + j], W[(k+1)*HH + j]);
            u64 W23 = pk2(W[(k+2)*HH + j], W[(k+3)*HH + j]);
            #pragma unroll
            for (int e = 0; e < 32; e++) {
                ulonglong2 a = *(const ulonglong2*)(base + e * SB_STR + k);
                ffma2(acc[e], a.x, W01);
                ffma2(acc[e], a.y, W23);
            }
        }
        #pragma unroll
        for (int e = 0; e < 32; e++) {
            int n = n0 + eg*32 + e;
            if (n < NN) g_PQ[(size_t)n * 256 + half * 128 + j] = hadd2(acc[e]);
        }
    }
}

// ============================================================
__device__ __forceinline__ void copy_weights(const __nv_bfloat16* __restrict__ ghi,
                                             const __nv_bfloat16* __restrict__ glo,
                                             __nv_bfloat16* sWhi, __nv_bfloat16* sWlo,
                                             int tid)
{
    const uint4* srcH = (const uint4*)ghi;
    const uint4* srcL = (const uint4*)glo;
    uint4* dstH = (uint4*)sWhi;
    uint4* dstL = (uint4*)sWlo;
    const int nvec = HH * WK * 2 / 16;    // 2176
    for (int i = tid; i < nvec; i += ETHREADS) {
        dstH[i] = srcH[i];
        dstL[i] = srcL[i];
    }
}

// MMA compute: 16 warps, warp w handles m-block (w&7)*16, n-half (w>>3)*64.
__device__ __forceinline__ void mma_compute(float (&acc)[32],
    const __nv_bfloat16* __restrict__ sAhi, const __nv_bfloat16* __restrict__ sAlo,
    const __nv_bfloat16* __restrict__ sWhi, const __nv_bfloat16* __restrict__ sWlo,
    int tid)
{
    const int w = tid >> 5, lane = tid & 31;
    const int g = lane >> 2, tig = lane & 3;
    const int m0 = (w & 7) * 16;
    const int nbase = (w >> 3) * 64;

    #pragma unroll
    for (int i = 0; i < 32; i++) acc[i] = 0.f;

    #pragma unroll
    for (int kb = 0; kb < 8; kb++) {
        const int k0 = kb * 16;
        const int ar = (m0 + g) * AK + k0 + 2 * tig;
        uint32_t ah0 = *(const uint32_t*)(sAhi + ar);
        uint32_t ah1 = *(const uint32_t*)(sAhi + ar + 8 * AK);
        uint32_t ah2 = *(const uint32_t*)(sAhi + ar + 8);
        uint32_t ah3 = *(const uint32_t*)(sAhi + ar + 8 * AK + 8);
        uint32_t al0 = *(const uint32_t*)(sAlo + ar);
        uint32_t al1 = *(const uint32_t*)(sAlo + ar + 8 * AK);
        uint32_t al2 = *(const uint32_t*)(sAlo + ar + 8);
        uint32_t al3 = *(const uint32_t*)(sAlo + ar + 8 * AK + 8);
        #pragma unroll
        for (int nb = 0; nb < 8; nb++) {
            const int n0 = nbase + nb * 8;
            const int br = (n0 + g) * WK + k0 + 2 * tig;
            uint32_t bh0 = *(const uint32_t*)(sWhi + br);
            uint32_t bh1 = *(const uint32_t*)(sWhi + br + 8);
            uint32_t bl0 = *(const uint32_t*)(sWlo + br);
            uint32_t bl1 = *(const uint32_t*)(sWlo + br + 8);
            mma16816(acc + nb*4, ah0, ah1, ah2, ah3, bh0, bh1);
            mma16816(acc + nb*4, ah0, ah1, ah2, ah3, bl0, bl1);
            mma16816(acc + nb*4, al0, al1, al2, al3, bh0, bh1);
        }
    }
}

// ============================================================
// Fused edge pass: 128 edges/tile, 512 threads
__global__ __launch_bounds__(ETHREADS, 1)
void edge_kernel(const float* __restrict__ u,
                 const float* __restrict__ v,
                 const float* __restrict__ edge_attr,
                 const float* __restrict__ W_e1, const float* __restrict__ b_e1,
                 const float* __restrict__ b_e2,
                 const float* __restrict__ b_c1,
                 const float* __restrict__ W_cl,
                 const int*   __restrict__ edge_index)
{
    extern __shared__ __align__(16) char smem[];
    float* sIn  = (float*)(smem + OFF_UNION);      // GEMM1 inputs (phase 1)
    u64*   sWcl = (u64*)  (smem + OFF_UNION);      // coordGEMM2 weights (phase 2)
    int*   sRow = (int*)  (smem + OFF_ROW);
    float* sRad = (float*)(smem + OFF_RAD);
    __nv_bfloat16* sAhi = (__nv_bfloat16*)(smem + OFF_AHI);
    __nv_bfloat16* sAlo = (__nv_bfloat16*)(smem + OFF_ALO);
    __nv_bfloat16* sWhi = (__nv_bfloat16*)(smem + OFF_WHI);
    __nv_bfloat16* sWlo = (__nv_bfloat16*)(smem + OFF_WLO);

    const int tid = threadIdx.x;
    const int e0  = blockIdx.x * ETILE;

    // ---- setup: copy We2 weights, gather PQ (bf16 split), w_diff, rad2 ----
    copy_weights(g_We2hi, g_We2lo, sWhi, sWlo, tid);

    {   // gather P[row]+Q[col] -> bf16 hi/lo directly
        int e = tid >> 2, sub = tid & 3;
        int gidx = e0 + e;
        int r = edge_index[gidx];
        int c = edge_index[EE + gidx];
        const float4* Pr = (const float4*)(g_PQ + (size_t)r * 256);
        const float4* Qc = (const float4*)(g_PQ + (size_t)c * 256 + 128);
        #pragma unroll
        for (int i = 0; i < 8; i++) {
            int f4 = sub + 4*i;
            float4 a = Pr[f4];
            float4 b = Qc[f4];
            float s0 = a.x+b.x, s1 = a.y+b.y, s2 = a.z+b.z, s3 = a.w+b.w;
            __nv_bfloat16 h0,l0,h1,l1;
            __nv_bfloat162 th, tl;
            bf16split(s0,h0,l0); bf16split(s1,h1,l1);
            th.x=h0; th.y=h1; tl.x=l0; tl.y=l1;
            int off = e * AK + 4 * f4;
            *(__nv_bfloat162*)(sAhi + off) = th;
            *(__nv_bfloat162*)(sAlo + off) = tl;
            bf16split(s2,h0,l0); bf16split(s3,h1,l1);
            th.x=h0; th.y=h1; tl.x=l0; tl.y=l1;
            *(__nv_bfloat162*)(sAhi + off + 2) = th;
            *(__nv_bfloat162*)(sAlo + off + 2) = tl;
        }
        if (sub == 0) {
            sRow[e] = r;
            sIn[e * SI_STR + 33] = edge_attr[gidx];
            sIn[e * SI_STR + 34] = 0.f;
            sIn[e * SI_STR + 35] = 0.f;
            atomicAdd(&g_cnt[r], 1.0f);
        }
    }

    for (int idx = tid; idx < ETILE * LVV; idx += ETHREADS) {   // w_diff
        int e = idx / LVV, lv = idx - e * LVV;
        int gidx = e0 + e;
        int r = edge_index[gidx], c = edge_index[EE + gidx];
        float ucv = u[c * LVV + lv], vcv = v[c * LVV + lv];
        float urv = u[r * LVV + lv], vrv = v[r * LVV + lv];
        float cs = sqrtf(ucv * ucv + vcv * vcv);
        float rs = sqrtf(urv * urv + vrv * vrv);
        float rd = (ucv * urv + vcv * vrv) / (cs * rs);
        float* rrow = sIn + e * SI_STR;
        rrow[0  + lv] = rd;
        rrow[11 + lv] = cs;
        rrow[22 + lv] = rs;
    }

    for (int e = tid; e < ETILE; e += ETHREADS) {               // rad2
        int gidx = e0 + e;
        int c = edge_index[EE + gidx];
        float su = 0.f, sv = 0.f;
        #pragma unroll
        for (int lv = 0; lv < LVV; lv++) {
            float a = u[c * LVV + lv], b = v[c * LVV + lv];
            su += a * a; sv += b * b;
        }
        sRad[e * 2 + 0] = sqrtf(su);
        sRad[e * 2 + 1] = sqrtf(sv);
    }
    __syncthreads();

    const int j  = tid & 127;
    const int eg = tid >> 7;       // 0..3, 32 rows each

    // ---- GEMM1 (34-k scalar): hid = relu(PQ + w_diff@W_e1[256:] + b_e1)
    //      reads PQ bf16 splits, overwrites SAME elements with hid splits ----
    {
        const float* W1w = W_e1 + 256 * HH;
        float bb = b_e1[j];
        float acc[32];
        #pragma unroll
        for (int e = 0; e < 32; e++) {
            int row = eg * 32 + e;
            acc[e] = __bfloat162float(sAhi[row * AK + j])
                   + __bfloat162float(sAlo[row * AK + j]) + bb;
        }
        const float* base = sIn + (eg * 32) * SI_STR;
        for (int k = 0; k < 32; k += 4) {
            float w0 = W1w[(k+0)*HH + j], w1 = W1w[(k+1)*HH + j];
            float w2 = W1w[(k+2)*HH + j], w3 = W1w[(k+3)*HH + j];
            #pragma unroll
            for (int e = 0; e < 32; e++) {
                float4 a = *(const float4*)(base + e * SI_STR + k);
                acc[e] += a.x*w0 + a.y*w1 + a.z*w2 + a.w*w3;
            }
        }
        {
            float w0 = W1w[32*HH + j], w1 = W1w[33*HH + j];
            #pragma unroll
            for (int e = 0; e < 32; e++) {
                const float* rr = base + e * SI_STR;
                acc[e] += rr[32]*w0 + rr[33]*w1;
            }
        }
        #pragma unroll
        for (int e = 0; e < 32; e++) {
            float hv = fmaxf(acc[e], 0.f);
            __nv_bfloat16 hi, lo; bf16split(hv, hi, lo);
            int row = eg * 32 + e;
            sAhi[row * AK + j] = hi;
            sAlo[row * AK + j] = lo;
        }
    }
    __syncthreads();

    // ---- GEMM2 (tensor): feat = relu(hid @ W_e2 + b_e2)
    //      epilogue: scatter to g_agg + write feat splits in place ----
    {
        float acc[32];
        mma_compute(acc, sAhi, sAlo, sWhi, sWlo, tid);
        __syncthreads();   // all MMA reads of sA/sW complete

        const int w = tid >> 5, lane = tid & 31;
        const int g = lane >> 2, tig = lane & 3;
        const int m0 = (w & 7) * 16;
        const int nbase = (w >> 3) * 64;
        const int r0 = sRow[m0 + g], r1 = sRow[m0 + g + 8];
        #pragma unroll
        for (int nb = 0; nb < 8; nb++) {
            const int n0 = nbase + nb * 8 + 2 * tig;
            float b0 = b_e2[n0], b1 = b_e2[n0 + 1];
            float v00 = fmaxf(acc[nb*4+0] + b0, 0.f);
            float v01 = fmaxf(acc[nb*4+1] + b1, 0.f);
            float v10 = fmaxf(acc[nb*4+2] + b0, 0.f);
            float v11 = fmaxf(acc[nb*4+3] + b1, 0.f);
            asm volatile("red.global.add.v2.f32 [%0], {%1,%2};"
                         :: "l"(g_agg + (size_t)r0 * HH + n0), "f"(v00), "f"(v01) : "memory");
            asm volatile("red.global.add.v2.f32 [%0], {%1,%2};"
                         :: "l"(g_agg + (size_t)r1 * HH + n0), "f"(v10), "f"(v11) : "memory");
            __nv_bfloat16 h0,l0,h1,l1;
            __nv_bfloat162 th, tl;
            bf16split(v00, h0, l0); bf16split(v01, h1, l1);
            th.x=h0; th.y=h1; tl.x=l0; tl.y=l1;
            *(__nv_bfloat162*)(sAhi + (m0 + g) * AK + n0) = th;
            *(__nv_bfloat162*)(sAlo + (m0 + g) * AK + n0) = tl;
            bf16split(v10, h0, l0); bf16split(v11, h1, l1);
            th.x=h0; th.y=h1; tl.x=l0; tl.y=l1;
            *(__nv_bfloat162*)(sAhi + (m0 + g + 8) * AK + n0) = th;
            *(__nv_bfloat162*)(sAlo + (m0 + g + 8) * AK + n0) = tl;
        }
    }

    // ---- swap weights to W_c1; fill sWcl (overwrites dead sIn) ----
    copy_weights(g_Wc1hi, g_Wc1lo, sWhi, sWlo, tid);
    for (int idx = tid; idx < 64 * 22; idx += ETHREADS) {
        int kk = idx / 22, m = idx - kk * 22;
        sWcl[idx] = pk2(W_cl[(2*kk) * 22 + m], W_cl[(2*kk+1) * 22 + m]);
    }
    __syncthreads();

    // ---- coord GEMM1 (tensor): c1 = relu(feat @ W_c1 + b_c1),
    //      write c1 bf16 splits back into sA ----
    {
        float acc[32];
        mma_compute(acc, sAhi, sAlo, sWhi, sWlo, tid);
        __syncthreads();   // all MMA reads of sA (feat) complete

        const int w = tid >> 5, lane = tid & 31;
        const int g = lane >> 2, tig = lane & 3;
        const int m0 = (w & 7) * 16;
        const int nbase = (w >> 3) * 64;
        #pragma unroll
        for (int nb = 0; nb < 8; nb++) {
            const int n0 = nbase + nb * 8 + 2 * tig;
            float b0 = b_c1[n0], b1 = b_c1[n0 + 1];
            float v00 = fmaxf(acc[nb*4+0] + b0, 0.f);
            float v01 = fmaxf(acc[nb*4+1] + b1, 0.f);
            float v10 = fmaxf(acc[nb*4+2] + b0, 0.f);
            float v11 = fmaxf(acc[nb*4+3] + b1, 0.f);
            __nv_bfloat16 h0,l0,h1,l1;
            __nv_bfloat162 th, tl;
            bf16split(v00, h0, l0); bf16split(v01, h1, l1);
            th.x=h0; th.y=h1; tl.x=l0; tl.y=l1;
            *(__nv_bfloat162*)(sAhi + (m0 + g) * AK + n0) = th;
            *(__nv_bfloat162*)(sAlo + (m0 + g) * AK + n0) = tl;
            bf16split(v10, h0, l0); bf16split(v11, h1, l1);
            th.x=h0; th.y=h1; tl.x=l0; tl.y=l1;
            *(__nv_bfloat162*)(sAhi + (m0 + g + 8) * AK + n0) = th;
            *(__nv_bfloat162*)(sAlo + (m0 + g + 8) * AK + n0) = tl;
        }
    }
    __syncthreads();

    // ---- coord GEMM2 (H->22, scalar) * rad2, scatter wind ----
    for (int idx = tid; idx < ETILE * 22; idx += ETHREADS) {
        int e = idx / 22, m = idx - e * 22;
        const __nv_bfloat162* bh = (const __nv_bfloat162*)(sAhi + e * AK);
        const __nv_bfloat162* bl = (const __nv_bfloat162*)(sAlo + e * AK);
        u64 acc = 0ULL;
        #pragma unroll 8
        for (int kk = 0; kk < 64; kk++) {
            float2 h2 = __bfloat1622float2(bh[kk]);
            float2 l2 = __bfloat1622float2(bl[kk]);
            u64 a = pk2(h2.x + l2.x, h2.y + l2.y);
            ffma2(acc, a, sWcl[kk * 22 + m]);
        }
        float r2 = sRad[e * 2 + (m >= 11 ? 1 : 0)];
        atomicAdd(&g_wind[(size_t)sRow[e] * 22 + m], hadd2(acc) * r2);
    }
}

// ============================================================
__global__ void lat_kernel() {
    int lt = blockIdx.x;
    int jj = threadIdx.x;
    float s = 0.f;
    for (int lon = 0; lon < NLON; lon++)
        s += g_agg[((size_t)lt * NLON + lon) * HH + jj];
    g_lat[lt * HH + jj] = s * (1.0f / NLON);
}

// ============================================================
__global__ __launch_bounds__(256, 3)
void node_kernel(const float* __restrict__ h,
                 const float* __restrict__ W_n1, const float* __restrict__ b_n1,
                 const float* __restrict__ W_n2, const float* __restrict__ b_n2,
                 float* __restrict__ out)
{
    extern __shared__ __align__(16) float smemf[];
    float* sA = smemf;
    float* sB = sA + NTILE * NA_STR;

    const int tid = threadIdx.x;
    const int n0  = blockIdx.x * NTILE;

    {
        int e = tid >> 3, sub = tid & 7;
        int n = n0 + e;
        float4* dst = (float4*)(sA + e * NA_STR);
        if (n < NN) {
            const float4* hh = (const float4*)(h + (size_t)n * HH);
            const float4* aa = (const float4*)(g_agg + (size_t)n * HH);
            const float4* ll = (const float4*)(g_lat + (size_t)(n / NLON) * HH);
            #pragma unroll
            for (int i = 0; i < 4; i++) {
                dst[sub + 8*i]      = hh[sub + 8*i];
                dst[32 + sub + 8*i] = aa[sub + 8*i];
                dst[64 + sub + 8*i] = ll[sub + 8*i];
            }
        } else {
            float4 z = make_float4(0.f, 0.f, 0.f, 0.f);
            #pragma unroll
            for (int i = 0; i < 4; i++) {
                dst[sub + 8*i] = z; dst[32 + sub + 8*i] = z; dst[64 + sub + 8*i] = z;
            }
        }
    }
    __syncthreads();

    const int j  = tid & 127;
    const int eg = tid >> 7;

    {
        u64 acc[16];
        #pragma unroll
        for (int e = 0; e < 16; e++) acc[e] = 0ULL;
        const float* base = sA + (eg * 16) * NA_STR;
        for (int k = 0; k < NA_STR; k += 4) {
            u64 W01 = pk2(W_n1[(k+0)*HH + j], W_n1[(k+1)*HH + j]);
            u64 W23 = pk2(W_n1[(k+2)*HH + j], W_n1[(k+3)*HH + j]);
            #pragma unroll
            for (int e = 0; e < 16; e++) {
                ulonglong2 a = *(const ulonglong2*)(base + e * NA_STR + k);
                ffma2(acc[e], a.x, W01);
                ffma2(acc[e], a.y, W23);
            }
        }
        float bb = b_n1[j];
        #pragma unroll
        for (int e = 0; e < 16; e++)
            sB[(eg*16 + e)*SB_STR + j] = fmaxf(hadd2(acc[e]) + bb, 0.f);
    }
    __syncthreads();

    {
        u64 acc[16];
        #pragma unroll
        for (int e = 0; e < 16; e++) acc[e] = 0ULL;
        const float* base = sB + (eg * 16) * SB_STR;
        for (int k = 0; k < 128; k += 4) {
            u64 W01 = pk2(W_n2[(k+0)*HH + j], W_n2[(k+1)*HH + j]);
            u64 W23 = pk2(W_n2[(k+2)*HH + j], W_n2[(k+3)*HH + j]);
            #pragma unroll
            for (int e = 0; e < 16; e++) {
                ulonglong2 a = *(const ulonglong2*)(base + e * SB_STR + k);
                ffma2(acc[e], a.x, W01);
                ffma2(acc[e], a.y, W23);
            }
        }
        float bb = b_n2[j];
        #pragma unroll
        for (int e = 0; e < 16; e++) {
            int n = n0 + eg*16 + e;
            if (n < NN)
                out[(size_t)n * HH + j] = hadd2(acc[e]) + bb + h[(size_t)n * HH + j];
        }
    }
}

// ============================================================
__global__ void coord_kernel(float* __restrict__ out) {
    int i = blockIdx.x * 256 + threadIdx.x;
    if (i >= NN * 22) return;
    int n = i / 22, m = i - n * 22;
    float cnt = fmaxf(g_cnt[n], 1.0f);
    float val = g_wind[i] / cnt;
    val = fminf(fmaxf(val, -100.0f), 100.0f);
    int lv = (m >= 11) ? (m - 11) : m;
    float* o = out + (size_t)NN * HH + (m >= 11 ? NN * LVV : 0) + n * LVV + lv;
    *o = val;
}

// ============================================================
extern "C" void kernel_launch(void* const* d_in, const int* in_sizes, int n_in,
                              void* d_out, int out_size)
{
    const float* h         = (const float*)d_in[0];
    const float* u         = (const float*)d_in[1];
    const float* v         = (const float*)d_in[2];
    const float* edge_attr = (const float*)d_in[3];
    const float* W_e1      = (const float*)d_in[4];
    const float* b_e1      = (const float*)d_in[5];
    const float* W_e2      = (const float*)d_in[6];
    const float* b_e2      = (const float*)d_in[7];
    const float* W_n1      = (const float*)d_in[8];
    const float* b_n1      = (const float*)d_in[9];
    const float* W_n2      = (const float*)d_in[10];
    const float* b_n2      = (const float*)d_in[11];
    const float* W_c1      = (const float*)d_in[12];
    const float* b_c1      = (const float*)d_in[13];
    const float* W_cl      = (const float*)d_in[14];
    const int*   edge_index= (const int*)  d_in[15];
    float* out = (float*)d_out;

    const int PQ_SMEM   = 64 * SB_STR * 4;
    const int NODE_SMEM = (NTILE * NA_STR + NTILE * SB_STR) * 4;
    cudaFuncSetAttribute(pq_kernel,   cudaFuncAttributeMaxDynamicSharedMemorySize, PQ_SMEM);
    cudaFuncSetAttribute(edge_kernel, cudaFuncAttributeMaxDynamicSharedMemorySize, EDGE_SMEM);
    cudaFuncSetAttribute(node_kernel, cudaFuncAttributeMaxDynamicSharedMemorySize, NODE_SMEM);

    zero_kernel<<<(NN * HH + 255) / 256, 256>>>();
    wsplit_kernel<<<(2 * HH * HH + 255) / 256, 256>>>(W_e2, W_c1);

    pq_kernel<<<(NN + 63) / 64, 256, PQ_SMEM>>>(h, W_e1);

    edge_kernel<<<EE / ETILE, ETHREADS, EDGE_SMEM>>>(u, v, edge_attr,
                                                     W_e1, b_e1, b_e2,
                                                     b_c1, W_cl, edge_index);

    lat_kernel<<<NLAT, HH>>>();

    node_kernel<<<(NN + NTILE - 1) / NTILE, 256, NODE_SMEM>>>(h, W_n1, b_n1, W_n2, b_n2, out);

    coord_kernel<<<(NN * 22 + 255) / 256, 256>>>(out);
}